// round 12
// baseline (speedup 1.0000x reference)
#include <cuda_runtime.h>
#include <cuda_fp16.h>
#include <math.h>
#include <stdint.h>

#define BATCH 32
#define TOK 197
#define ROWS (BATCH*TOK)
#define MPAD 6400
#define DIM 768
#define HEADS 12
#define DHD 64
#define FFD 3072
#define QKVD 2304
#define NPATCH 196
#define PATCH_ROWS (BATCH*NPATCH)
#define NCLSD 1000
#define KP2_D (2*DIM)
#define KP2_F (2*FFD)
#define LO_SCALE 2048.0f
#define LO_INV   (1.0f/2048.0f)

__device__ float  g_x   [ROWS*DIM];
__device__ __align__(128) __half g_q16 [BATCH*HEADS*TOK*DHD];
__device__ __align__(128) __half g_k16 [BATCH*HEADS*TOK*DHD];
__device__ __align__(128) __half g_v16 [BATCH*HEADS*TOK*DHD];
__device__ float  g_tok [PATCH_ROWS*DIM];
__device__ float  g_hh  [BATCH*FFD];
__device__ __align__(128) __half g_a16 [MPAD*KP2_D];
__device__ __align__(128) __half g_f16 [(size_t)MPAD*KP2_F];
__device__ __align__(128) __half g_wp16  [DIM*DIM];
__device__ __align__(128) __half g_wqkv16[(size_t)12*QKVD*DIM];
__device__ __align__(128) __half g_wpr16 [(size_t)12*DIM*DIM];
__device__ __align__(128) __half g_wf1_16[(size_t)12*FFD*DIM];
__device__ __align__(128) __half g_wf2_16[(size_t)12*DIM*FFD];

__device__ __forceinline__ uint32_t smem_u32(const void* p) {
    uint32_t a;
    asm("{ .reg .u64 t; cvta.to.shared.u64 t, %1; cvt.u32.u64 %0, t; }" : "=r"(a) : "l"(p));
    return a;
}
__device__ __forceinline__ void cp_async16(uint32_t s, const void* g) {
    asm volatile("cp.async.cg.shared.global [%0], [%1], 16;\n" :: "r"(s), "l"(g));
}
#define CP_COMMIT() asm volatile("cp.async.commit_group;\n" ::: "memory")
#define CP_WAIT(n)  asm volatile("cp.async.wait_group %0;\n" :: "n"(n) : "memory")

__device__ __forceinline__ void ldsm_x4(uint32_t& r0, uint32_t& r1, uint32_t& r2, uint32_t& r3,
                                        uint32_t addr) {
    asm volatile("ldmatrix.sync.aligned.m8n8.x4.shared.b16 {%0,%1,%2,%3}, [%4];"
                 : "=r"(r0), "=r"(r1), "=r"(r2), "=r"(r3) : "r"(addr));
}
__device__ __forceinline__ void mma16816(float* c, const uint32_t* a, const uint32_t* b) {
    asm volatile("mma.sync.aligned.m16n8k16.row.col.f32.f16.f16.f32 "
        "{%0,%1,%2,%3}, {%4,%5,%6,%7}, {%8,%9}, {%0,%1,%2,%3};"
        : "+f"(c[0]), "+f"(c[1]), "+f"(c[2]), "+f"(c[3])
        : "r"(a[0]), "r"(a[1]), "r"(a[2]), "r"(a[3]), "r"(b[0]), "r"(b[1]));
}
// fp16-accumulate MMA (2x rate): D,C are 2 x .f16x2 regs
__device__ __forceinline__ void mma16816_h(uint32_t* c, const uint32_t* a, const uint32_t* b) {
    asm volatile("mma.sync.aligned.m16n8k16.row.col.f16.f16.f16.f16 "
        "{%0,%1}, {%2,%3,%4,%5}, {%6,%7}, {%0,%1};"
        : "+r"(c[0]), "+r"(c[1])
        : "r"(a[0]), "r"(a[1]), "r"(a[2]), "r"(a[3]), "r"(b[0]), "r"(b[1]));
}
__device__ __forceinline__ float gelu_f(float v) {
    return 0.5f * v * (1.0f + erff(v * 0.70710678118654752f));
}
__device__ __forceinline__ float wred_sum(float v) {
#pragma unroll
    for (int o = 16; o > 0; o >>= 1) v += __shfl_xor_sync(0xffffffffu, v, o);
    return v;
}

// ===== split-fp16 HMMA GEMM: BM=128 BN=128, Kc=64, 2-stage, f16-acc correction =====
#define STG 49152
#define HG_SMEM (2*STG)

__global__ __launch_bounds__(256, 2) void hgemm(
    const __half* __restrict__ A, const __half* __restrict__ B, int K,
    const float* __restrict__ bias, const float* __restrict__ res,
    float* __restrict__ outF, __half* __restrict__ out16,
    __half* __restrict__ gq, __half* __restrict__ gk, __half* __restrict__ gv,
    int ldc, int M, int mode)
{
    extern __shared__ char smraw[];
    uint32_t smb = smem_u32(smraw);
    int tid = threadIdx.x;
    int lane = tid & 31, wid = tid >> 5;
    int warp_m = wid & 1, warp_n = wid >> 1;
    int row0 = blockIdx.y * 128, col0 = blockIdx.x * 128;

    uint32_t ld_slot[4]; int ld_r[4], ld_c[4];
#pragma unroll
    for (int j = 0; j < 4; j++) {
        int idx = tid + j * 256;
        ld_r[j] = idx >> 3; ld_c[j] = idx & 7;
        ld_slot[j] = (uint32_t)(ld_r[j] * 128 + ((ld_c[j] ^ (ld_r[j] & 7)) << 4));
    }

    int g = lane >> 3, l = lane & 7;
    uint32_t a_roff[4], a_xor[4];
#pragma unroll
    for (int mi = 0; mi < 4; mi++) {
        int r = warp_m * 64 + mi * 16 + (g & 1) * 8 + l;
        a_roff[mi] = r * 128; a_xor[mi] = r & 7;
    }
    uint32_t b_roff[2], b_xor[2];
#pragma unroll
    for (int j2 = 0; j2 < 2; j2++) {
        int r = warp_n * 32 + j2 * 16 + (g >> 1) * 8 + l;
        b_roff[j2] = r * 128; b_xor[j2] = r & 7;
    }

    float acc[4][4][4];
    uint32_t acc16[4][4][2];
#pragma unroll
    for (int mi = 0; mi < 4; mi++)
#pragma unroll
        for (int nj = 0; nj < 4; nj++) {
#pragma unroll
            for (int q = 0; q < 4; q++) acc[mi][nj][q] = 0.f;
            acc16[mi][nj][0] = 0u; acc16[mi][nj][1] = 0u;
        }

    const int KT = K >> 6;
    const size_t strA = (size_t)(2 * K);
    const size_t strB = (size_t)K;
    const __half* gA = A + (size_t)row0 * strA;
    const __half* gB = B + (size_t)col0 * strB;

#define LOAD_ST(s, kb) do { \
    uint32_t sa = smb + (uint32_t)(s) * STG; \
    _Pragma("unroll") \
    for (int j = 0; j < 4; j++) { \
        const __half* pa = gA + (size_t)ld_r[j] * strA + (size_t)(kb) * 64 + ld_c[j] * 8; \
        cp_async16(sa + ld_slot[j], pa); \
        cp_async16(sa + 16384u + ld_slot[j], pa + K); \
        cp_async16(sa + 32768u + ld_slot[j], gB + (size_t)ld_r[j] * strB + (size_t)(kb) * 64 + ld_c[j] * 8); \
    } \
} while (0)

    LOAD_ST(0, 0); CP_COMMIT();

    for (int i = 0; i < KT; i++) {
        CP_WAIT(0);
        __syncthreads();
        if (i + 1 < KT) { LOAD_ST((i + 1) & 1, i + 1); CP_COMMIT(); }

        uint32_t ah_b = smb + (uint32_t)(i & 1) * STG;
        uint32_t al_b = ah_b + 16384u;
        uint32_t bh_b = ah_b + 32768u;
#pragma unroll
        for (int ks = 0; ks < 4; ks++) {
            uint32_t cha = (uint32_t)(ks * 2 + (g >> 1));
            uint32_t chb = (uint32_t)(ks * 2 + (g & 1));
            uint32_t bf[4][2];
#pragma unroll
            for (int j2 = 0; j2 < 2; j2++)
                ldsm_x4(bf[j2 * 2][0], bf[j2 * 2][1], bf[j2 * 2 + 1][0], bf[j2 * 2 + 1][1],
                        bh_b + b_roff[j2] + ((chb ^ b_xor[j2]) << 4));
            // per-mi: load Ah frag -> 4 f32-acc MMAs; load Al frag -> 4 f16-acc MMAs
#pragma unroll
            for (int mi = 0; mi < 4; mi++) {
                uint32_t af[4];
                ldsm_x4(af[0], af[1], af[2], af[3],
                        ah_b + a_roff[mi] + ((cha ^ a_xor[mi]) << 4));
#pragma unroll
                for (int nj = 0; nj < 4; nj++)
                    mma16816(acc[mi][nj], af, bf[nj]);
                ldsm_x4(af[0], af[1], af[2], af[3],
                        al_b + a_roff[mi] + ((cha ^ a_xor[mi]) << 4));
#pragma unroll
                for (int nj = 0; nj < 4; nj++)
                    mma16816_h(acc16[mi][nj], af, bf[nj]);
            }
        }
    }

    int qrow = lane >> 2, qcol = (lane & 3) * 2;
#pragma unroll
    for (int mi = 0; mi < 4; mi++) {
        int rbase = row0 + warp_m * 64 + mi * 16 + qrow;
#pragma unroll
        for (int half = 0; half < 2; half++) {
            int r = rbase + half * 8;
            if (r >= M) continue;
            int rb = r / TOK, rn = r - rb * TOK;
#pragma unroll
            for (int nj = 0; nj < 4; nj++) {
                int c = col0 + warp_n * 32 + nj * 8 + qcol;
                float2 cf = __half22float2(*(__half2*)&acc16[mi][nj][half]);
                float v0 = acc[mi][nj][half * 2 + 0] + cf.x * LO_INV + __ldg(bias + c);
                float v1 = acc[mi][nj][half * 2 + 1] + cf.y * LO_INV + __ldg(bias + c + 1);
                if (mode == 2) {
                    float g0 = gelu_f(v0), g1 = gelu_f(v1);
                    __half h0 = __float2half(g0), h1 = __float2half(g1);
                    __half l0 = __float2half((g0 - __half2float(h0)) * LO_SCALE);
                    __half l1 = __float2half((g1 - __half2float(h1)) * LO_SCALE);
                    __half* o = out16 + (size_t)r * (2 * ldc) + c;
                    *(__half2*)(o)       = __halves2half2(h0, h1);
                    *(__half2*)(o + ldc) = __halves2half2(l0, l1);
                } else if (mode == 3) {
#pragma unroll
                    for (int e = 0; e < 2; e++) {
                        int cc = c + e;
                        float vv = e ? v1 : v0;
                        int hh = cc / 192;
                        int t  = cc - hh * 192;
                        int dd = t / 3;
                        int ss = t - dd * 3;
                        __half* dst = (ss == 0) ? gq : (ss == 1) ? gk : gv;
                        dst[(((size_t)(rb * HEADS + hh)) * TOK + rn) * DHD + dd] = __float2half(vv);
                    }
                } else {
                    float* o = outF + (size_t)r * ldc + c;
                    if (mode == 1) {
                        const float* rr = res + (size_t)r * ldc + c;
                        v0 += rr[0]; v1 += rr[1];
                    }
                    *(float2*)o = make_float2(v0, v1);
                }
            }
        }
    }
}

// ===== hgemm_bm64: BM=64, BN=128 (tail-friendly), f16-acc correction =====
#define STGB 32768
#define HGB_SMEM (2*STGB)

__global__ __launch_bounds__(256, 2) void hgemm_bm64(
    const __half* __restrict__ A, const __half* __restrict__ B, int K,
    const float* __restrict__ bias, const float* __restrict__ res,
    float* __restrict__ outF, int ldc, int M, int mode)
{
    extern __shared__ char smraw[];
    uint32_t smb = smem_u32(smraw);
    int tid = threadIdx.x;
    int lane = tid & 31, wid = tid >> 5;
    int warp_m = wid & 1, warp_n = wid >> 1;
    int row0 = blockIdx.y * 64, col0 = blockIdx.x * 128;

    uint32_t ld_slot[4]; int ld_r[4], ld_c[4];
#pragma unroll
    for (int j = 0; j < 4; j++) {
        int idx = tid + j * 256;
        ld_r[j] = idx >> 3; ld_c[j] = idx & 7;
        ld_slot[j] = (uint32_t)(ld_r[j] * 128 + ((ld_c[j] ^ (ld_r[j] & 7)) << 4));
    }

    int g = lane >> 3, l = lane & 7;
    uint32_t a_roff[2], a_xor[2];
#pragma unroll
    for (int mi = 0; mi < 2; mi++) {
        int r = warp_m * 32 + mi * 16 + (g & 1) * 8 + l;
        a_roff[mi] = r * 128; a_xor[mi] = r & 7;
    }
    uint32_t b_roff[2], b_xor[2];
#pragma unroll
    for (int j2 = 0; j2 < 2; j2++) {
        int r = warp_n * 32 + j2 * 16 + (g >> 1) * 8 + l;
        b_roff[j2] = r * 128; b_xor[j2] = r & 7;
    }

    float acc[2][4][4];
    uint32_t acc16[2][4][2];
#pragma unroll
    for (int mi = 0; mi < 2; mi++)
#pragma unroll
        for (int nj = 0; nj < 4; nj++) {
#pragma unroll
            for (int q = 0; q < 4; q++) acc[mi][nj][q] = 0.f;
            acc16[mi][nj][0] = 0u; acc16[mi][nj][1] = 0u;
        }

    const int KT = K >> 6;
    const size_t strA = (size_t)(2 * K);
    const size_t strB = (size_t)K;
    const __half* gA = A + (size_t)row0 * strA;
    const __half* gB = B + (size_t)col0 * strB;

#define LOAD_STB(s, kb) do { \
    uint32_t sa = smb + (uint32_t)(s) * STGB; \
    _Pragma("unroll") \
    for (int j = 0; j < 2; j++) { \
        const __half* pa = gA + (size_t)ld_r[j] * strA + (size_t)(kb) * 64 + ld_c[j] * 8; \
        cp_async16(sa + ld_slot[j], pa); \
        cp_async16(sa + 8192u + ld_slot[j], pa + K); \
    } \
    _Pragma("unroll") \
    for (int j = 0; j < 4; j++) { \
        cp_async16(sa + 16384u + ld_slot[j], gB + (size_t)ld_r[j] * strB + (size_t)(kb) * 64 + ld_c[j] * 8); \
    } \
} while (0)

    LOAD_STB(0, 0); CP_COMMIT();

    for (int i = 0; i < KT; i++) {
        CP_WAIT(0);
        __syncthreads();
        if (i + 1 < KT) { LOAD_STB((i + 1) & 1, i + 1); CP_COMMIT(); }

        uint32_t ah_b = smb + (uint32_t)(i & 1) * STGB;
        uint32_t al_b = ah_b + 8192u;
        uint32_t bh_b = ah_b + 16384u;
#pragma unroll
        for (int ks = 0; ks < 4; ks++) {
            uint32_t cha = (uint32_t)(ks * 2 + (g >> 1));
            uint32_t chb = (uint32_t)(ks * 2 + (g & 1));
            uint32_t bf[4][2];
#pragma unroll
            for (int j2 = 0; j2 < 2; j2++)
                ldsm_x4(bf[j2 * 2][0], bf[j2 * 2][1], bf[j2 * 2 + 1][0], bf[j2 * 2 + 1][1],
                        bh_b + b_roff[j2] + ((chb ^ b_xor[j2]) << 4));
#pragma unroll
            for (int mi = 0; mi < 2; mi++) {
                uint32_t af[4];
                ldsm_x4(af[0], af[1], af[2], af[3],
                        ah_b + a_roff[mi] + ((cha ^ a_xor[mi]) << 4));
#pragma unroll
                for (int nj = 0; nj < 4; nj++)
                    mma16816(acc[mi][nj], af, bf[nj]);
                ldsm_x4(af[0], af[1], af[2], af[3],
                        al_b + a_roff[mi] + ((cha ^ a_xor[mi]) << 4));
#pragma unroll
                for (int nj = 0; nj < 4; nj++)
                    mma16816_h(acc16[mi][nj], af, bf[nj]);
            }
        }
    }

    int qrow = lane >> 2, qcol = (lane & 3) * 2;
#pragma unroll
    for (int mi = 0; mi < 2; mi++) {
        int rbase = row0 + warp_m * 32 + mi * 16 + qrow;
#pragma unroll
        for (int half = 0; half < 2; half++) {
            int r = rbase + half * 8;
            if (r >= M) continue;
#pragma unroll
            for (int nj = 0; nj < 4; nj++) {
                int c = col0 + warp_n * 32 + nj * 8 + qcol;
                float2 cf = __half22float2(*(__half2*)&acc16[mi][nj][half]);
                float v0 = acc[mi][nj][half * 2 + 0] + cf.x * LO_INV + __ldg(bias + c);
                float v1 = acc[mi][nj][half * 2 + 1] + cf.y * LO_INV + __ldg(bias + c + 1);
                float* o = outF + (size_t)r * ldc + c;
                if (mode == 1) {
                    const float* rr = res + (size_t)r * ldc + c;
                    v0 += rr[0]; v1 += rr[1];
                }
                *(float2*)o = make_float2(v0, v1);
            }
        }
    }
}

// ===== helpers (lo pre-scaled by 2048) =====
__global__ void convert_w(const float4* __restrict__ W, __half2* __restrict__ W16, long total4)
{
    long idx = (long)blockIdx.x * blockDim.x + threadIdx.x;
    if (idx >= total4) return;
    float4 v = W[idx];
    W16[idx * 2]     = __halves2half2(__float2half(v.x), __float2half(v.y));
    W16[idx * 2 + 1] = __halves2half2(__float2half(v.z), __float2half(v.w));
}

__global__ __launch_bounds__(256) void ln_split_warp(
    const float* __restrict__ x, const float* __restrict__ w,
    const float* __restrict__ b, __half* __restrict__ y16)
{
    int row = blockIdx.x * 8 + (threadIdx.x >> 5);
    if (row >= ROWS) return;
    int lane = threadIdx.x & 31;
    const float4* xr = (const float4*)(x + (size_t)row * DIM);
    float4 vx[6];
    float s = 0.f;
#pragma unroll
    for (int i = 0; i < 6; i++) {
        vx[i] = xr[lane + 32 * i];
        s += (vx[i].x + vx[i].y) + (vx[i].z + vx[i].w);
    }
    s = wred_sum(s);
    float mean = s * (1.0f / 768.f);
    float s2 = 0.f;
#pragma unroll
    for (int i = 0; i < 6; i++) {
        float a0 = vx[i].x - mean, a1 = vx[i].y - mean;
        float a2 = vx[i].z - mean, a3 = vx[i].w - mean;
        s2 += a0 * a0 + a1 * a1 + a2 * a2 + a3 * a3;
    }
    s2 = wred_sum(s2);
    float inv = rsqrtf(s2 * (1.0f / 768.f) + 1e-5f);
    const float4* wr = (const float4*)w;
    const float4* br = (const float4*)b;
    __half2* yh = (__half2*)(y16 + (size_t)row * KP2_D);
    __half2* yl = (__half2*)(y16 + (size_t)row * KP2_D + DIM);
#pragma unroll
    for (int i = 0; i < 6; i++) {
        int c4 = lane + 32 * i;
        float4 w4 = wr[c4], b4 = br[c4];
        float v0 = (vx[i].x - mean) * inv * w4.x + b4.x;
        float v1 = (vx[i].y - mean) * inv * w4.y + b4.y;
        float v2 = (vx[i].z - mean) * inv * w4.z + b4.z;
        float v3 = (vx[i].w - mean) * inv * w4.w + b4.w;
        __half h0 = __float2half(v0), h1 = __float2half(v1);
        __half h2 = __float2half(v2), h3 = __float2half(v3);
        yh[c4 * 2]     = __halves2half2(h0, h1);
        yh[c4 * 2 + 1] = __halves2half2(h2, h3);
        yl[c4 * 2]     = __halves2half2(__float2half((v0 - __half2float(h0)) * LO_SCALE),
                                        __float2half((v1 - __half2float(h1)) * LO_SCALE));
        yl[c4 * 2 + 1] = __halves2half2(__float2half((v2 - __half2float(h2)) * LO_SCALE),
                                        __float2half((v3 - __half2float(h3)) * LO_SCALE));
    }
}

__global__ void im2col_split(const float* __restrict__ img, __half* __restrict__ a16)
{
    int idx = blockIdx.x * blockDim.x + threadIdx.x;
    if (idx >= PATCH_ROWS * DIM) return;
    int e = idx % DIM;
    int m = idx / DIM;
    int b = m / NPATCH, p = m % NPATCH;
    int gr = p / 14, gc = p % 14;
    int c = e % 3;
    int pp = e / 3;
    int pr = pp / 16, pc = pp % 16;
    float v = img[(((size_t)b * 3 + c) * 224 + gr * 16 + pr) * 224 + gc * 16 + pc];
    __half hi = __float2half(v);
    __half* dst = a16 + (size_t)m * KP2_D;
    dst[e] = hi;
    dst[DIM + e] = __float2half((v - __half2float(hi)) * LO_SCALE);
}

__global__ void assemble_kernel(const float* __restrict__ tokens,
                                const float* __restrict__ cls,
                                const float* __restrict__ pos,
                                float* __restrict__ x)
{
    int idx = blockIdx.x * blockDim.x + threadIdx.x;
    if (idx >= ROWS * DIM) return;
    int d = idx % DIM;
    int r = idx / DIM;
    int b = r / TOK, n = r % TOK;
    float v = (n == 0) ? cls[d] : tokens[((size_t)b * NPATCH + (n - 1)) * DIM + d];
    x[idx] = v + pos[(size_t)n * DIM + d];
}

// ===== attention: 2 queries per warp, fp16 K/V in smem =====
#define ATT_PAD 33
#define ATT2_SMEM ((2*TOK*ATT_PAD + 16*ATT_PAD) * 4 + 16*200*4)

__global__ __launch_bounds__(256) void attn2(
    const __half* __restrict__ Q, const __half* __restrict__ K,
    const __half* __restrict__ V, __half* __restrict__ a16)
{
    extern __shared__ char smraw[];
    __half2* ks2 = (__half2*)smraw;
    __half2* vs2 = ks2 + TOK * ATT_PAD;
    __half2* qs2 = vs2 + TOK * ATT_PAD;
    float*   sc  = (float*)(qs2 + 16 * ATT_PAD);

    int bh = blockIdx.x;
    int b = bh / HEADS, h = bh % HEADS;
    int tid = threadIdx.x, lane = tid & 31, w = tid >> 5;
    const __half2* Qb = (const __half2*)(Q + (size_t)bh * TOK * DHD);
    const __half2* Kb = (const __half2*)(K + (size_t)bh * TOK * DHD);
    const __half2* Vb = (const __half2*)(V + (size_t)bh * TOK * DHD);

    for (int i = tid; i < TOK * 32; i += 256) {
        int n = i >> 5, d2 = i & 31;
        ks2[n * ATT_PAD + d2] = Kb[i];
        vs2[n * ATT_PAD + d2] = Vb[i];
    }
    __syncthreads();

    float* scw0 = sc + w * 400;
    float* scw1 = scw0 + 200;
    __half2* q0 = qs2 + (w * 2) * ATT_PAD;
    __half2* q1 = q0 + ATT_PAD;

    for (int base = 0; base < TOK; base += 16) {
        int nq0 = base + w * 2, nq1 = nq0 + 1;
        bool ok0 = (nq0 < TOK), ok1 = (nq1 < TOK);
        if (ok0) q0[lane] = Qb[(size_t)nq0 * 32 + lane];
        if (ok1) q1[lane] = Qb[(size_t)nq1 * 32 + lane];
        __syncwarp();
        if (!ok0) { continue; }
        float mx0 = -1e30f, mx1 = -1e30f;
        for (int kk = lane; kk < TOK; kk += 32) {
            float s0 = 0.f, s1 = 0.f;
#pragma unroll
            for (int d2 = 0; d2 < 32; d2++) {
                float2 kv  = __half22float2(ks2[kk * ATT_PAD + d2]);
                float2 qv0 = __half22float2(q0[d2]);
                float2 qv1 = __half22float2(q1[d2]);
                s0 += kv.x * qv0.x + kv.y * qv0.y;
                s1 += kv.x * qv1.x + kv.y * qv1.y;
            }
            scw0[kk] = s0 * 0.125f;
            scw1[kk] = s1 * 0.125f;
            mx0 = fmaxf(mx0, s0 * 0.125f);
            mx1 = fmaxf(mx1, s1 * 0.125f);
        }
#pragma unroll
        for (int o = 16; o > 0; o >>= 1) {
            mx0 = fmaxf(mx0, __shfl_xor_sync(0xffffffffu, mx0, o));
            mx1 = fmaxf(mx1, __shfl_xor_sync(0xffffffffu, mx1, o));
        }
        float sum0 = 0.f, sum1 = 0.f;
        for (int kk = lane; kk < TOK; kk += 32) {
            float p0 = expf(scw0[kk] - mx0);
            float p1 = expf(scw1[kk] - mx1);
            scw0[kk] = p0; scw1[kk] = p1;
            sum0 += p0; sum1 += p1;
        }
        sum0 = wred_sum(sum0); sum1 = wred_sum(sum1);
        float inv0 = 1.f / sum0, inv1 = 1.f / sum1;
        __syncwarp();
        float ax0 = 0.f, ay0 = 0.f, ax1 = 0.f, ay1 = 0.f;
        for (int kk = 0; kk < TOK; kk++) {
            float2 vv = __half22float2(vs2[kk * ATT_PAD + lane]);
            float p0 = scw0[kk], p1 = scw1[kk];
            ax0 += p0 * vv.x; ay0 += p0 * vv.y;
            ax1 += p1 * vv.x; ay1 += p1 * vv.y;
        }
        ax0 *= inv0; ay0 *= inv0; ax1 *= inv1; ay1 *= inv1;
        {
            size_t o0 = ((size_t)(b * TOK + nq0)) * KP2_D + h * DHD + lane * 2;
            __half h0 = __float2half(ax0), h1 = __float2half(ay0);
            a16[o0] = h0; a16[o0 + 1] = h1;
            a16[o0 + DIM]     = __float2half((ax0 - __half2float(h0)) * LO_SCALE);
            a16[o0 + DIM + 1] = __float2half((ay0 - __half2float(h1)) * LO_SCALE);
        }
        if (ok1) {
            size_t o1 = ((size_t)(b * TOK + nq1)) * KP2_D + h * DHD + lane * 2;
            __half h0 = __float2half(ax1), h1 = __float2half(ay1);
            a16[o1] = h0; a16[o1 + 1] = h1;
            a16[o1 + DIM]     = __float2half((ax1 - __half2float(h0)) * LO_SCALE);
            a16[o1 + DIM + 1] = __float2half((ay1 - __half2float(h1)) * LO_SCALE);
        }
        __syncwarp();
    }
}

// fp32 SGEMM for the tiny head (M=32)
__global__ __launch_bounds__(256) void sgemm(
    const float* __restrict__ A, int lda,
    const float* __restrict__ W, const float* __restrict__ bias,
    float* __restrict__ C, int ldc, int M, int N, int K, int act)
{
    __shared__ float As[16][128];
    __shared__ float Bs[16][64];
    int tid = threadIdx.x;
    int tx = tid & 15, ty = tid >> 4;
    int row0 = blockIdx.y * 128;
    int col0 = blockIdx.x * 64;
    float acc[8][4];
#pragma unroll
    for (int i = 0; i < 8; i++)
#pragma unroll
        for (int j = 0; j < 4; j++) acc[i][j] = 0.f;
    for (int k0 = 0; k0 < K; k0 += 16) {
#pragma unroll
        for (int i = 0; i < 2; i++) {
            int idx = tid + i * 256;
            int r = idx >> 2, c = (idx & 3) << 2;
            int gr = row0 + r;
            float4 v = make_float4(0.f, 0.f, 0.f, 0.f);
            if (gr < M) v = *(const float4*)(A + (size_t)gr * lda + k0 + c);
            As[c + 0][r] = v.x; As[c + 1][r] = v.y; As[c + 2][r] = v.z; As[c + 3][r] = v.w;
        }
        {
            int n = tid >> 2, c = (tid & 3) << 2;
            int gn = col0 + n;
            float4 v = make_float4(0.f, 0.f, 0.f, 0.f);
            if (gn < N) v = *(const float4*)(W + (size_t)gn * K + k0 + c);
            Bs[c + 0][n] = v.x; Bs[c + 1][n] = v.y; Bs[c + 2][n] = v.z; Bs[c + 3][n] = v.w;
        }
        __syncthreads();
#pragma unroll
        for (int kk = 0; kk < 16; kk++) {
            float4 a0 = *(const float4*)&As[kk][ty * 8];
            float4 a1 = *(const float4*)&As[kk][ty * 8 + 4];
            float4 bb = *(const float4*)&Bs[kk][tx * 4];
            float av[8] = {a0.x, a0.y, a0.z, a0.w, a1.x, a1.y, a1.z, a1.w};
            float bv[4] = {bb.x, bb.y, bb.z, bb.w};
#pragma unroll
            for (int i = 0; i < 8; i++)
#pragma unroll
                for (int j = 0; j < 4; j++) acc[i][j] += av[i] * bv[j];
        }
        __syncthreads();
    }
#pragma unroll
    for (int i = 0; i < 8; i++) {
        int gr = row0 + ty * 8 + i;
        if (gr >= M) continue;
#pragma unroll
        for (int j = 0; j < 4; j++) {
            int gn = col0 + tx * 4 + j;
            if (gn >= N) continue;
            float v = acc[i][j];
            if (bias) v += bias[gn];
            if (act == 2) v = tanhf(v);
            C[(size_t)gr * ldc + gn] = v;
        }
    }
}

extern "C" void kernel_launch(void* const* d_in, const int* in_sizes, int n_in,
                              void* d_out, int out_size)
{
    const float* img     = (const float*)d_in[0];
    const float* patch_w = (const float*)d_in[1];
    const float* patch_b = (const float*)d_in[2];
    const float* cls_tok = (const float*)d_in[3];
    const float* pos_emb = (const float*)d_in[4];
    const float* ln1_w   = (const float*)d_in[5];
    const float* ln1_b   = (const float*)d_in[6];
    const float* qkv_w   = (const float*)d_in[7];
    const float* qkv_b   = (const float*)d_in[8];
    const float* proj_w  = (const float*)d_in[9];
    const float* proj_b  = (const float*)d_in[10];
    const float* ln2_w   = (const float*)d_in[11];
    const float* ln2_b   = (const float*)d_in[12];
    const float* ff1_w   = (const float*)d_in[13];
    const float* ff1_b   = (const float*)d_in[14];
    const float* ff2_w   = (const float*)d_in[15];
    const float* ff2_b   = (const float*)d_in[16];
    const float* head1_w = (const float*)d_in[17];
    const float* head1_b = (const float*)d_in[18];
    const float* head2_w = (const float*)d_in[19];
    const float* head2_b = (const float*)d_in[20];
    float* out = (float*)d_out;

    float *x, *tok, *hh;
    __half *q, *k, *v, *a16, *f16, *wp, *wq, *wpr, *wf1, *wf2;
    cudaGetSymbolAddress((void**)&x,   g_x);
    cudaGetSymbolAddress((void**)&q,   g_q16);
    cudaGetSymbolAddress((void**)&k,   g_k16);
    cudaGetSymbolAddress((void**)&v,   g_v16);
    cudaGetSymbolAddress((void**)&tok, g_tok);
    cudaGetSymbolAddress((void**)&hh,  g_hh);
    cudaGetSymbolAddress((void**)&a16, g_a16);
    cudaGetSymbolAddress((void**)&f16, g_f16);
    cudaGetSymbolAddress((void**)&wp,  g_wp16);
    cudaGetSymbolAddress((void**)&wq,  g_wqkv16);
    cudaGetSymbolAddress((void**)&wpr, g_wpr16);
    cudaGetSymbolAddress((void**)&wf1, g_wf1_16);
    cudaGetSymbolAddress((void**)&wf2, g_wf2_16);

    cudaFuncSetAttribute(hgemm,      cudaFuncAttributeMaxDynamicSharedMemorySize, HG_SMEM);
    cudaFuncSetAttribute(hgemm_bm64, cudaFuncAttributeMaxDynamicSharedMemorySize, HGB_SMEM);
    cudaFuncSetAttribute(attn2,      cudaFuncAttributeMaxDynamicSharedMemorySize, ATT2_SMEM);

    long t4;
    t4 = (long)DIM * DIM / 4;
    convert_w<<<(unsigned)((t4 + 255) / 256), 256>>>((const float4*)patch_w, (__half2*)wp, t4);
    t4 = 12L * QKVD * DIM / 4;
    convert_w<<<(unsigned)((t4 + 255) / 256), 256>>>((const float4*)qkv_w, (__half2*)wq, t4);
    t4 = 12L * DIM * DIM / 4;
    convert_w<<<(unsigned)((t4 + 255) / 256), 256>>>((const float4*)proj_w, (__half2*)wpr, t4);
    t4 = 12L * FFD * DIM / 4;
    convert_w<<<(unsigned)((t4 + 255) / 256), 256>>>((const float4*)ff1_w, (__half2*)wf1, t4);
    t4 = 12L * DIM * FFD / 4;
    convert_w<<<(unsigned)((t4 + 255) / 256), 256>>>((const float4*)ff2_w, (__half2*)wf2, t4);

    {
        int tot = PATCH_ROWS * DIM;
        im2col_split<<<(tot + 255) / 256, 256>>>(img, a16);
        hgemm<<<dim3(6, 49), 256, HG_SMEM>>>(a16, wp, DIM, patch_b, (const float*)0,
                                             tok, (__half*)0, (__half*)0, (__half*)0, (__half*)0,
                                             DIM, PATCH_ROWS, 0);
        int tot2 = ROWS * DIM;
        assemble_kernel<<<(tot2 + 255) / 256, 256>>>(tok, cls_tok, pos_emb, x);
    }

    for (int l = 0; l < 12; l++) {
        ln_split_warp<<<(ROWS + 7) / 8, 256>>>(x, ln1_w + (size_t)l * DIM, ln1_b + (size_t)l * DIM, a16);
        hgemm<<<dim3(18, 50), 256, HG_SMEM>>>(a16, wq + (size_t)l * QKVD * DIM, DIM,
                                              qkv_b + (size_t)l * QKVD, (const float*)0,
                                              (float*)0, (__half*)0, q, k, v,
                                              QKVD, ROWS, 3);
        attn2<<<BATCH * HEADS, 256, ATT2_SMEM>>>(q, k, v, a16);
        hgemm_bm64<<<dim3(6, 99), 256, HGB_SMEM>>>(a16, wpr + (size_t)l * DIM * DIM, DIM,
                                                   proj_b + (size_t)l * DIM, x,
                                                   x, DIM, ROWS, 1);
        ln_split_warp<<<(ROWS + 7) / 8, 256>>>(x, ln2_w + (size_t)l * DIM, ln2_b + (size_t)l * DIM, a16);
        hgemm<<<dim3(24, 50), 256, HG_SMEM>>>(a16, wf1 + (size_t)l * FFD * DIM, DIM,
                                              ff1_b + (size_t)l * FFD, (const float*)0,
                                              (float*)0, f16, (__half*)0, (__half*)0, (__half*)0,
                                              FFD, ROWS, 2);
        hgemm_bm64<<<dim3(6, 99), 256, HGB_SMEM>>>(f16, wf2 + (size_t)l * DIM * FFD, FFD,
                                                   ff2_b + (size_t)l * DIM, x,
                                                   x, DIM, ROWS, 1);
    }

    sgemm<<<dim3(48, 1), 256>>>(x, TOK * DIM, head1_w, head1_b, hh, FFD, BATCH, FFD, DIM, 2);
    sgemm<<<dim3(16, 1), 256>>>(hh, FFD, head2_w, head2_b, out, NCLSD, BATCH, NCLSD, FFD, 0);
}

// round 13
// speedup vs baseline: 1.0822x; 1.0822x over previous
#include <cuda_runtime.h>
#include <cuda_fp16.h>
#include <math.h>
#include <stdint.h>

#define BATCH 32
#define TOK 197
#define ROWS (BATCH*TOK)
#define MPAD 6400
#define DIM 768
#define HEADS 12
#define DHD 64
#define FFD 3072
#define QKVD 2304
#define NPATCH 196
#define PATCH_ROWS (BATCH*NPATCH)
#define NCLSD 1000
#define KP2_D (2*DIM)
#define KP2_F (2*FFD)

__device__ float  g_x   [ROWS*DIM];
__device__ __align__(128) __half g_q16 [BATCH*HEADS*TOK*DHD];
__device__ __align__(128) __half g_k16 [BATCH*HEADS*TOK*DHD];
__device__ __align__(128) __half g_v16 [BATCH*HEADS*TOK*DHD];
__device__ float  g_tok [PATCH_ROWS*DIM];
__device__ float  g_hh  [BATCH*FFD];
__device__ __align__(128) __half g_a16 [MPAD*KP2_D];
__device__ __align__(128) __half g_f16 [(size_t)MPAD*KP2_F];
__device__ __align__(128) __half g_wp16  [DIM*DIM];
__device__ __align__(128) __half g_wqkv16[(size_t)12*QKVD*DIM];
__device__ __align__(128) __half g_wpr16 [(size_t)12*DIM*DIM];
__device__ __align__(128) __half g_wf1_16[(size_t)12*FFD*DIM];
__device__ __align__(128) __half g_wf2_16[(size_t)12*DIM*FFD];

__device__ __forceinline__ uint32_t smem_u32(const void* p) {
    uint32_t a;
    asm("{ .reg .u64 t; cvta.to.shared.u64 t, %1; cvt.u32.u64 %0, t; }" : "=r"(a) : "l"(p));
    return a;
}
__device__ __forceinline__ void cp_async16(uint32_t s, const void* g) {
    asm volatile("cp.async.cg.shared.global [%0], [%1], 16;\n" :: "r"(s), "l"(g));
}
#define CP_COMMIT() asm volatile("cp.async.commit_group;\n" ::: "memory")
#define CP_WAIT(n)  asm volatile("cp.async.wait_group %0;\n" :: "n"(n) : "memory")

__device__ __forceinline__ void ldsm_x4(uint32_t& r0, uint32_t& r1, uint32_t& r2, uint32_t& r3,
                                        uint32_t addr) {
    asm volatile("ldmatrix.sync.aligned.m8n8.x4.shared.b16 {%0,%1,%2,%3}, [%4];"
                 : "=r"(r0), "=r"(r1), "=r"(r2), "=r"(r3) : "r"(addr));
}
__device__ __forceinline__ void mma16816(float* c, const uint32_t* a, const uint32_t* b) {
    asm volatile("mma.sync.aligned.m16n8k16.row.col.f32.f16.f16.f32 "
        "{%0,%1,%2,%3}, {%4,%5,%6,%7}, {%8,%9}, {%0,%1,%2,%3};"
        : "+f"(c[0]), "+f"(c[1]), "+f"(c[2]), "+f"(c[3])
        : "r"(a[0]), "r"(a[1]), "r"(a[2]), "r"(a[3]), "r"(b[0]), "r"(b[1]));
}
__device__ __forceinline__ float gelu_f(float v) {
    return 0.5f * v * (1.0f + erff(v * 0.70710678118654752f));
}
__device__ __forceinline__ float wred_sum(float v) {
#pragma unroll
    for (int o = 16; o > 0; o >>= 1) v += __shfl_xor_sync(0xffffffffu, v, o);
    return v;
}

// ===== split-fp16 HMMA GEMM: BM=128 BN=128, Kc=64, 2-stage =====
// lo=1: two products (Ah*B + Al*B); lo=0: single product (fp16 GEMM, A stride still 2K)
#define STG 49152
#define HG_SMEM (2*STG)

__global__ __launch_bounds__(256, 2) void hgemm(
    const __half* __restrict__ A, const __half* __restrict__ B, int K,
    const float* __restrict__ bias, const float* __restrict__ res,
    float* __restrict__ outF, __half* __restrict__ out16,
    __half* __restrict__ gq, __half* __restrict__ gk, __half* __restrict__ gv,
    int ldc, int M, int mode, int lo)
{
    extern __shared__ char smraw[];
    uint32_t smb = smem_u32(smraw);
    int tid = threadIdx.x;
    int lane = tid & 31, wid = tid >> 5;
    int warp_m = wid & 1, warp_n = wid >> 1;
    int row0 = blockIdx.y * 128, col0 = blockIdx.x * 128;

    uint32_t ld_slot[4]; int ld_r[4], ld_c[4];
#pragma unroll
    for (int j = 0; j < 4; j++) {
        int idx = tid + j * 256;
        ld_r[j] = idx >> 3; ld_c[j] = idx & 7;
        ld_slot[j] = (uint32_t)(ld_r[j] * 128 + ((ld_c[j] ^ (ld_r[j] & 7)) << 4));
    }

    int g = lane >> 3, l = lane & 7;
    uint32_t a_roff[4], a_xor[4];
#pragma unroll
    for (int mi = 0; mi < 4; mi++) {
        int r = warp_m * 64 + mi * 16 + (g & 1) * 8 + l;
        a_roff[mi] = r * 128; a_xor[mi] = r & 7;
    }
    uint32_t b_roff[2], b_xor[2];
#pragma unroll
    for (int j2 = 0; j2 < 2; j2++) {
        int r = warp_n * 32 + j2 * 16 + (g >> 1) * 8 + l;
        b_roff[j2] = r * 128; b_xor[j2] = r & 7;
    }

    float acc[4][4][4];
#pragma unroll
    for (int mi = 0; mi < 4; mi++)
#pragma unroll
        for (int nj = 0; nj < 4; nj++)
#pragma unroll
            for (int q = 0; q < 4; q++) acc[mi][nj][q] = 0.f;

    const int KT = K >> 6;
    const size_t strA = (size_t)(2 * K);
    const size_t strB = (size_t)K;
    const __half* gA = A + (size_t)row0 * strA;
    const __half* gB = B + (size_t)col0 * strB;

#define LOAD_ST(s, kb) do { \
    uint32_t sa = smb + (uint32_t)(s) * STG; \
    _Pragma("unroll") \
    for (int j = 0; j < 4; j++) { \
        const __half* pa = gA + (size_t)ld_r[j] * strA + (size_t)(kb) * 64 + ld_c[j] * 8; \
        cp_async16(sa + ld_slot[j], pa); \
        if (lo) cp_async16(sa + 16384u + ld_slot[j], pa + K); \
        cp_async16(sa + 32768u + ld_slot[j], gB + (size_t)ld_r[j] * strB + (size_t)(kb) * 64 + ld_c[j] * 8); \
    } \
} while (0)

    LOAD_ST(0, 0); CP_COMMIT();

    for (int i = 0; i < KT; i++) {
        CP_WAIT(0);
        __syncthreads();
        if (i + 1 < KT) { LOAD_ST((i + 1) & 1, i + 1); CP_COMMIT(); }

        uint32_t ah_b = smb + (uint32_t)(i & 1) * STG;
        uint32_t al_b = ah_b + 16384u;
        uint32_t bh_b = ah_b + 32768u;
#pragma unroll
        for (int ks = 0; ks < 4; ks++) {
            uint32_t cha = (uint32_t)(ks * 2 + (g >> 1));
            uint32_t chb = (uint32_t)(ks * 2 + (g & 1));
            uint32_t afh[4][4], bf[4][2];
#pragma unroll
            for (int mi = 0; mi < 4; mi++)
                ldsm_x4(afh[mi][0], afh[mi][1], afh[mi][2], afh[mi][3],
                        ah_b + a_roff[mi] + ((cha ^ a_xor[mi]) << 4));
#pragma unroll
            for (int j2 = 0; j2 < 2; j2++)
                ldsm_x4(bf[j2 * 2][0], bf[j2 * 2][1], bf[j2 * 2 + 1][0], bf[j2 * 2 + 1][1],
                        bh_b + b_roff[j2] + ((chb ^ b_xor[j2]) << 4));
#pragma unroll
            for (int mi = 0; mi < 4; mi++)
#pragma unroll
                for (int nj = 0; nj < 4; nj++)
                    mma16816(acc[mi][nj], afh[mi], bf[nj]);
            if (lo) {
                uint32_t afl[4][4];
#pragma unroll
                for (int mi = 0; mi < 4; mi++)
                    ldsm_x4(afl[mi][0], afl[mi][1], afl[mi][2], afl[mi][3],
                            al_b + a_roff[mi] + ((cha ^ a_xor[mi]) << 4));
#pragma unroll
                for (int mi = 0; mi < 4; mi++)
#pragma unroll
                    for (int nj = 0; nj < 4; nj++)
                        mma16816(acc[mi][nj], afl[mi], bf[nj]);
            }
        }
    }

    int qrow = lane >> 2, qcol = (lane & 3) * 2;
#pragma unroll
    for (int mi = 0; mi < 4; mi++) {
        int rbase = row0 + warp_m * 64 + mi * 16 + qrow;
#pragma unroll
        for (int half = 0; half < 2; half++) {
            int r = rbase + half * 8;
            if (r >= M) continue;
            int rb = r / TOK, rn = r - rb * TOK;
#pragma unroll
            for (int nj = 0; nj < 4; nj++) {
                int c = col0 + warp_n * 32 + nj * 8 + qcol;
                float v0 = acc[mi][nj][half * 2 + 0] + __ldg(bias + c);
                float v1 = acc[mi][nj][half * 2 + 1] + __ldg(bias + c + 1);
                if (mode == 2) {
                    float g0 = gelu_f(v0), g1 = gelu_f(v1);
                    __half h0 = __float2half(g0), h1 = __float2half(g1);
                    __half l0 = __float2half(g0 - __half2float(h0));
                    __half l1 = __float2half(g1 - __half2float(h1));
                    __half* o = out16 + (size_t)r * (2 * ldc) + c;
                    *(__half2*)(o)       = __halves2half2(h0, h1);
                    *(__half2*)(o + ldc) = __halves2half2(l0, l1);
                } else if (mode == 3) {
#pragma unroll
                    for (int e = 0; e < 2; e++) {
                        int cc = c + e;
                        float vv = e ? v1 : v0;
                        int hh = cc / 192;
                        int t  = cc - hh * 192;
                        int dd = t / 3;
                        int ss = t - dd * 3;
                        __half* dst = (ss == 0) ? gq : (ss == 1) ? gk : gv;
                        dst[(((size_t)(rb * HEADS + hh)) * TOK + rn) * DHD + dd] = __float2half(vv);
                    }
                } else {
                    float* o = outF + (size_t)r * ldc + c;
                    if (mode == 1) {
                        const float* rr = res + (size_t)r * ldc + c;
                        v0 += rr[0]; v1 += rr[1];
                    }
                    *(float2*)o = make_float2(v0, v1);
                }
            }
        }
    }
}

// ===== hgemm_bm64: BM=64, BN=128 (tail-friendly), always two products =====
#define STGB 32768
#define HGB_SMEM (2*STGB)

__global__ __launch_bounds__(256, 2) void hgemm_bm64(
    const __half* __restrict__ A, const __half* __restrict__ B, int K,
    const float* __restrict__ bias, const float* __restrict__ res,
    float* __restrict__ outF, int ldc, int M, int mode)
{
    extern __shared__ char smraw[];
    uint32_t smb = smem_u32(smraw);
    int tid = threadIdx.x;
    int lane = tid & 31, wid = tid >> 5;
    int warp_m = wid & 1, warp_n = wid >> 1;
    int row0 = blockIdx.y * 64, col0 = blockIdx.x * 128;

    uint32_t ld_slot[4]; int ld_r[4], ld_c[4];
#pragma unroll
    for (int j = 0; j < 4; j++) {
        int idx = tid + j * 256;
        ld_r[j] = idx >> 3; ld_c[j] = idx & 7;
        ld_slot[j] = (uint32_t)(ld_r[j] * 128 + ((ld_c[j] ^ (ld_r[j] & 7)) << 4));
    }

    int g = lane >> 3, l = lane & 7;
    uint32_t a_roff[2], a_xor[2];
#pragma unroll
    for (int mi = 0; mi < 2; mi++) {
        int r = warp_m * 32 + mi * 16 + (g & 1) * 8 + l;
        a_roff[mi] = r * 128; a_xor[mi] = r & 7;
    }
    uint32_t b_roff[2], b_xor[2];
#pragma unroll
    for (int j2 = 0; j2 < 2; j2++) {
        int r = warp_n * 32 + j2 * 16 + (g >> 1) * 8 + l;
        b_roff[j2] = r * 128; b_xor[j2] = r & 7;
    }

    float acc[2][4][4];
#pragma unroll
    for (int mi = 0; mi < 2; mi++)
#pragma unroll
        for (int nj = 0; nj < 4; nj++)
#pragma unroll
            for (int q = 0; q < 4; q++) acc[mi][nj][q] = 0.f;

    const int KT = K >> 6;
    const size_t strA = (size_t)(2 * K);
    const size_t strB = (size_t)K;
    const __half* gA = A + (size_t)row0 * strA;
    const __half* gB = B + (size_t)col0 * strB;

#define LOAD_STB(s, kb) do { \
    uint32_t sa = smb + (uint32_t)(s) * STGB; \
    _Pragma("unroll") \
    for (int j = 0; j < 2; j++) { \
        const __half* pa = gA + (size_t)ld_r[j] * strA + (size_t)(kb) * 64 + ld_c[j] * 8; \
        cp_async16(sa + ld_slot[j], pa); \
        cp_async16(sa + 8192u + ld_slot[j], pa + K); \
    } \
    _Pragma("unroll") \
    for (int j = 0; j < 4; j++) { \
        cp_async16(sa + 16384u + ld_slot[j], gB + (size_t)ld_r[j] * strB + (size_t)(kb) * 64 + ld_c[j] * 8); \
    } \
} while (0)

    LOAD_STB(0, 0); CP_COMMIT();

    for (int i = 0; i < KT; i++) {
        CP_WAIT(0);
        __syncthreads();
        if (i + 1 < KT) { LOAD_STB((i + 1) & 1, i + 1); CP_COMMIT(); }

        uint32_t ah_b = smb + (uint32_t)(i & 1) * STGB;
        uint32_t al_b = ah_b + 8192u;
        uint32_t bh_b = ah_b + 16384u;
#pragma unroll
        for (int ks = 0; ks < 4; ks++) {
            uint32_t cha = (uint32_t)(ks * 2 + (g >> 1));
            uint32_t chb = (uint32_t)(ks * 2 + (g & 1));
            uint32_t afh[2][4], afl[2][4], bf[4][2];
#pragma unroll
            for (int mi = 0; mi < 2; mi++)
                ldsm_x4(afh[mi][0], afh[mi][1], afh[mi][2], afh[mi][3],
                        ah_b + a_roff[mi] + ((cha ^ a_xor[mi]) << 4));
#pragma unroll
            for (int j2 = 0; j2 < 2; j2++)
                ldsm_x4(bf[j2 * 2][0], bf[j2 * 2][1], bf[j2 * 2 + 1][0], bf[j2 * 2 + 1][1],
                        bh_b + b_roff[j2] + ((chb ^ b_xor[j2]) << 4));
#pragma unroll
            for (int mi = 0; mi < 2; mi++)
                ldsm_x4(afl[mi][0], afl[mi][1], afl[mi][2], afl[mi][3],
                        al_b + a_roff[mi] + ((cha ^ a_xor[mi]) << 4));
#pragma unroll
            for (int mi = 0; mi < 2; mi++)
#pragma unroll
                for (int nj = 0; nj < 4; nj++)
                    mma16816(acc[mi][nj], afh[mi], bf[nj]);
#pragma unroll
            for (int mi = 0; mi < 2; mi++)
#pragma unroll
                for (int nj = 0; nj < 4; nj++)
                    mma16816(acc[mi][nj], afl[mi], bf[nj]);
        }
    }

    int qrow = lane >> 2, qcol = (lane & 3) * 2;
#pragma unroll
    for (int mi = 0; mi < 2; mi++) {
        int rbase = row0 + warp_m * 32 + mi * 16 + qrow;
#pragma unroll
        for (int half = 0; half < 2; half++) {
            int r = rbase + half * 8;
            if (r >= M) continue;
#pragma unroll
            for (int nj = 0; nj < 4; nj++) {
                int c = col0 + warp_n * 32 + nj * 8 + qcol;
                float v0 = acc[mi][nj][half * 2 + 0] + __ldg(bias + c);
                float v1 = acc[mi][nj][half * 2 + 1] + __ldg(bias + c + 1);
                float* o = outF + (size_t)r * ldc + c;
                if (mode == 1) {
                    const float* rr = res + (size_t)r * ldc + c;
                    v0 += rr[0]; v1 += rr[1];
                }
                *(float2*)o = make_float2(v0, v1);
            }
        }
    }
}

// ===== helpers =====
__global__ void convert_w(const float4* __restrict__ W, __half2* __restrict__ W16, long total4)
{
    long idx = (long)blockIdx.x * blockDim.x + threadIdx.x;
    if (idx >= total4) return;
    float4 v = W[idx];
    W16[idx * 2]     = __halves2half2(__float2half(v.x), __float2half(v.y));
    W16[idx * 2 + 1] = __halves2half2(__float2half(v.z), __float2half(v.w));
}

__global__ __launch_bounds__(256) void ln_split_warp(
    const float* __restrict__ x, const float* __restrict__ w,
    const float* __restrict__ b, __half* __restrict__ y16)
{
    int row = blockIdx.x * 8 + (threadIdx.x >> 5);
    if (row >= ROWS) return;
    int lane = threadIdx.x & 31;
    const float4* xr = (const float4*)(x + (size_t)row * DIM);
    float4 vx[6];
    float s = 0.f;
#pragma unroll
    for (int i = 0; i < 6; i++) {
        vx[i] = xr[lane + 32 * i];
        s += (vx[i].x + vx[i].y) + (vx[i].z + vx[i].w);
    }
    s = wred_sum(s);
    float mean = s * (1.0f / 768.f);
    float s2 = 0.f;
#pragma unroll
    for (int i = 0; i < 6; i++) {
        float a0 = vx[i].x - mean, a1 = vx[i].y - mean;
        float a2 = vx[i].z - mean, a3 = vx[i].w - mean;
        s2 += a0 * a0 + a1 * a1 + a2 * a2 + a3 * a3;
    }
    s2 = wred_sum(s2);
    float inv = rsqrtf(s2 * (1.0f / 768.f) + 1e-5f);
    const float4* wr = (const float4*)w;
    const float4* br = (const float4*)b;
    __half2* yh = (__half2*)(y16 + (size_t)row * KP2_D);
    __half2* yl = (__half2*)(y16 + (size_t)row * KP2_D + DIM);
#pragma unroll
    for (int i = 0; i < 6; i++) {
        int c4 = lane + 32 * i;
        float4 w4 = wr[c4], b4 = br[c4];
        float v0 = (vx[i].x - mean) * inv * w4.x + b4.x;
        float v1 = (vx[i].y - mean) * inv * w4.y + b4.y;
        float v2 = (vx[i].z - mean) * inv * w4.z + b4.z;
        float v3 = (vx[i].w - mean) * inv * w4.w + b4.w;
        __half h0 = __float2half(v0), h1 = __float2half(v1);
        __half h2 = __float2half(v2), h3 = __float2half(v3);
        yh[c4 * 2]     = __halves2half2(h0, h1);
        yh[c4 * 2 + 1] = __halves2half2(h2, h3);
        yl[c4 * 2]     = __halves2half2(__float2half(v0 - __half2float(h0)),
                                        __float2half(v1 - __half2float(h1)));
        yl[c4 * 2 + 1] = __halves2half2(__float2half(v2 - __half2float(h2)),
                                        __float2half(v3 - __half2float(h3)));
    }
}

__global__ void im2col_split(const float* __restrict__ img, __half* __restrict__ a16)
{
    int idx = blockIdx.x * blockDim.x + threadIdx.x;
    if (idx >= PATCH_ROWS * DIM) return;
    int e = idx % DIM;
    int m = idx / DIM;
    int b = m / NPATCH, p = m % NPATCH;
    int gr = p / 14, gc = p % 14;
    int c = e % 3;
    int pp = e / 3;
    int pr = pp / 16, pc = pp % 16;
    float v = img[(((size_t)b * 3 + c) * 224 + gr * 16 + pr) * 224 + gc * 16 + pc];
    __half hi = __float2half(v);
    __half* dst = a16 + (size_t)m * KP2_D;
    dst[e] = hi;
    dst[DIM + e] = __float2half(v - __half2float(hi));
}

__global__ void assemble_kernel(const float* __restrict__ tokens,
                                const float* __restrict__ cls,
                                const float* __restrict__ pos,
                                float* __restrict__ x)
{
    int idx = blockIdx.x * blockDim.x + threadIdx.x;
    if (idx >= ROWS * DIM) return;
    int d = idx % DIM;
    int r = idx / DIM;
    int b = r / TOK, n = r % TOK;
    float v = (n == 0) ? cls[d] : tokens[((size_t)b * NPATCH + (n - 1)) * DIM + d];
    x[idx] = v + pos[(size_t)n * DIM + d];
}

// ===== attention: 2 queries per warp, fp16 K/V in smem =====
#define ATT_PAD 33
#define ATT2_SMEM ((2*TOK*ATT_PAD + 16*ATT_PAD) * 4 + 16*200*4)

__global__ __launch_bounds__(256) void attn2(
    const __half* __restrict__ Q, const __half* __restrict__ K,
    const __half* __restrict__ V, __half* __restrict__ a16)
{
    extern __shared__ char smraw[];
    __half2* ks2 = (__half2*)smraw;
    __half2* vs2 = ks2 + TOK * ATT_PAD;
    __half2* qs2 = vs2 + TOK * ATT_PAD;
    float*   sc  = (float*)(qs2 + 16 * ATT_PAD);

    int bh = blockIdx.x;
    int b = bh / HEADS, h = bh % HEADS;
    int tid = threadIdx.x, lane = tid & 31, w = tid >> 5;
    const __half2* Qb = (const __half2*)(Q + (size_t)bh * TOK * DHD);
    const __half2* Kb = (const __half2*)(K + (size_t)bh * TOK * DHD);
    const __half2* Vb = (const __half2*)(V + (size_t)bh * TOK * DHD);

    for (int i = tid; i < TOK * 32; i += 256) {
        int n = i >> 5, d2 = i & 31;
        ks2[n * ATT_PAD + d2] = Kb[i];
        vs2[n * ATT_PAD + d2] = Vb[i];
    }
    __syncthreads();

    float* scw0 = sc + w * 400;
    float* scw1 = scw0 + 200;
    __half2* q0 = qs2 + (w * 2) * ATT_PAD;
    __half2* q1 = q0 + ATT_PAD;

    for (int base = 0; base < TOK; base += 16) {
        int nq0 = base + w * 2, nq1 = nq0 + 1;
        bool ok0 = (nq0 < TOK), ok1 = (nq1 < TOK);
        if (ok0) q0[lane] = Qb[(size_t)nq0 * 32 + lane];
        if (ok1) q1[lane] = Qb[(size_t)nq1 * 32 + lane];
        __syncwarp();
        if (!ok0) { continue; }
        float mx0 = -1e30f, mx1 = -1e30f;
        for (int kk = lane; kk < TOK; kk += 32) {
            float s0 = 0.f, s1 = 0.f;
#pragma unroll
            for (int d2 = 0; d2 < 32; d2++) {
                float2 kv  = __half22float2(ks2[kk * ATT_PAD + d2]);
                float2 qv0 = __half22float2(q0[d2]);
                float2 qv1 = __half22float2(q1[d2]);
                s0 += kv.x * qv0.x + kv.y * qv0.y;
                s1 += kv.x * qv1.x + kv.y * qv1.y;
            }
            scw0[kk] = s0 * 0.125f;
            scw1[kk] = s1 * 0.125f;
            mx0 = fmaxf(mx0, s0 * 0.125f);
            mx1 = fmaxf(mx1, s1 * 0.125f);
        }
#pragma unroll
        for (int o = 16; o > 0; o >>= 1) {
            mx0 = fmaxf(mx0, __shfl_xor_sync(0xffffffffu, mx0, o));
            mx1 = fmaxf(mx1, __shfl_xor_sync(0xffffffffu, mx1, o));
        }
        float sum0 = 0.f, sum1 = 0.f;
        for (int kk = lane; kk < TOK; kk += 32) {
            float p0 = expf(scw0[kk] - mx0);
            float p1 = expf(scw1[kk] - mx1);
            scw0[kk] = p0; scw1[kk] = p1;
            sum0 += p0; sum1 += p1;
        }
        sum0 = wred_sum(sum0); sum1 = wred_sum(sum1);
        float inv0 = 1.f / sum0, inv1 = 1.f / sum1;
        __syncwarp();
        float ax0 = 0.f, ay0 = 0.f, ax1 = 0.f, ay1 = 0.f;
        for (int kk = 0; kk < TOK; kk++) {
            float2 vv = __half22float2(vs2[kk * ATT_PAD + lane]);
            float p0 = scw0[kk], p1 = scw1[kk];
            ax0 += p0 * vv.x; ay0 += p0 * vv.y;
            ax1 += p1 * vv.x; ay1 += p1 * vv.y;
        }
        ax0 *= inv0; ay0 *= inv0; ax1 *= inv1; ay1 *= inv1;
        {
            size_t o0 = ((size_t)(b * TOK + nq0)) * KP2_D + h * DHD + lane * 2;
            __half h0 = __float2half(ax0), h1 = __float2half(ay0);
            a16[o0] = h0; a16[o0 + 1] = h1;
            a16[o0 + DIM]     = __float2half(ax0 - __half2float(h0));
            a16[o0 + DIM + 1] = __float2half(ay0 - __half2float(h1));
        }
        if (ok1) {
            size_t o1 = ((size_t)(b * TOK + nq1)) * KP2_D + h * DHD + lane * 2;
            __half h0 = __float2half(ax1), h1 = __float2half(ay1);
            a16[o1] = h0; a16[o1 + 1] = h1;
            a16[o1 + DIM]     = __float2half(ax1 - __half2float(h0));
            a16[o1 + DIM + 1] = __float2half(ay1 - __half2float(h1));
        }
        __syncwarp();
    }
}

// fp32 SGEMM for the tiny head (M=32)
__global__ __launch_bounds__(256) void sgemm(
    const float* __restrict__ A, int lda,
    const float* __restrict__ W, const float* __restrict__ bias,
    float* __restrict__ C, int ldc, int M, int N, int K, int act)
{
    __shared__ float As[16][128];
    __shared__ float Bs[16][64];
    int tid = threadIdx.x;
    int tx = tid & 15, ty = tid >> 4;
    int row0 = blockIdx.y * 128;
    int col0 = blockIdx.x * 64;
    float acc[8][4];
#pragma unroll
    for (int i = 0; i < 8; i++)
#pragma unroll
        for (int j = 0; j < 4; j++) acc[i][j] = 0.f;
    for (int k0 = 0; k0 < K; k0 += 16) {
#pragma unroll
        for (int i = 0; i < 2; i++) {
            int idx = tid + i * 256;
            int r = idx >> 2, c = (idx & 3) << 2;
            int gr = row0 + r;
            float4 v = make_float4(0.f, 0.f, 0.f, 0.f);
            if (gr < M) v = *(const float4*)(A + (size_t)gr * lda + k0 + c);
            As[c + 0][r] = v.x; As[c + 1][r] = v.y; As[c + 2][r] = v.z; As[c + 3][r] = v.w;
        }
        {
            int n = tid >> 2, c = (tid & 3) << 2;
            int gn = col0 + n;
            float4 v = make_float4(0.f, 0.f, 0.f, 0.f);
            if (gn < N) v = *(const float4*)(W + (size_t)gn * K + k0 + c);
            Bs[c + 0][n] = v.x; Bs[c + 1][n] = v.y; Bs[c + 2][n] = v.z; Bs[c + 3][n] = v.w;
        }
        __syncthreads();
#pragma unroll
        for (int kk = 0; kk < 16; kk++) {
            float4 a0 = *(const float4*)&As[kk][ty * 8];
            float4 a1 = *(const float4*)&As[kk][ty * 8 + 4];
            float4 bb = *(const float4*)&Bs[kk][tx * 4];
            float av[8] = {a0.x, a0.y, a0.z, a0.w, a1.x, a1.y, a1.z, a1.w};
            float bv[4] = {bb.x, bb.y, bb.z, bb.w};
#pragma unroll
            for (int i = 0; i < 8; i++)
#pragma unroll
                for (int j = 0; j < 4; j++) acc[i][j] += av[i] * bv[j];
        }
        __syncthreads();
    }
#pragma unroll
    for (int i = 0; i < 8; i++) {
        int gr = row0 + ty * 8 + i;
        if (gr >= M) continue;
#pragma unroll
        for (int j = 0; j < 4; j++) {
            int gn = col0 + tx * 4 + j;
            if (gn >= N) continue;
            float v = acc[i][j];
            if (bias) v += bias[gn];
            if (act == 2) v = tanhf(v);
            C[(size_t)gr * ldc + gn] = v;
        }
    }
}

extern "C" void kernel_launch(void* const* d_in, const int* in_sizes, int n_in,
                              void* d_out, int out_size)
{
    const float* img     = (const float*)d_in[0];
    const float* patch_w = (const float*)d_in[1];
    const float* patch_b = (const float*)d_in[2];
    const float* cls_tok = (const float*)d_in[3];
    const float* pos_emb = (const float*)d_in[4];
    const float* ln1_w   = (const float*)d_in[5];
    const float* ln1_b   = (const float*)d_in[6];
    const float* qkv_w   = (const float*)d_in[7];
    const float* qkv_b   = (const float*)d_in[8];
    const float* proj_w  = (const float*)d_in[9];
    const float* proj_b  = (const float*)d_in[10];
    const float* ln2_w   = (const float*)d_in[11];
    const float* ln2_b   = (const float*)d_in[12];
    const float* ff1_w   = (const float*)d_in[13];
    const float* ff1_b   = (const float*)d_in[14];
    const float* ff2_w   = (const float*)d_in[15];
    const float* ff2_b   = (const float*)d_in[16];
    const float* head1_w = (const float*)d_in[17];
    const float* head1_b = (const float*)d_in[18];
    const float* head2_w = (const float*)d_in[19];
    const float* head2_b = (const float*)d_in[20];
    float* out = (float*)d_out;

    float *x, *tok, *hh;
    __half *q, *k, *v, *a16, *f16, *wp, *wq, *wpr, *wf1, *wf2;
    cudaGetSymbolAddress((void**)&x,   g_x);
    cudaGetSymbolAddress((void**)&q,   g_q16);
    cudaGetSymbolAddress((void**)&k,   g_k16);
    cudaGetSymbolAddress((void**)&v,   g_v16);
    cudaGetSymbolAddress((void**)&tok, g_tok);
    cudaGetSymbolAddress((void**)&hh,  g_hh);
    cudaGetSymbolAddress((void**)&a16, g_a16);
    cudaGetSymbolAddress((void**)&f16, g_f16);
    cudaGetSymbolAddress((void**)&wp,  g_wp16);
    cudaGetSymbolAddress((void**)&wq,  g_wqkv16);
    cudaGetSymbolAddress((void**)&wpr, g_wpr16);
    cudaGetSymbolAddress((void**)&wf1, g_wf1_16);
    cudaGetSymbolAddress((void**)&wf2, g_wf2_16);

    cudaFuncSetAttribute(hgemm,      cudaFuncAttributeMaxDynamicSharedMemorySize, HG_SMEM);
    cudaFuncSetAttribute(hgemm_bm64, cudaFuncAttributeMaxDynamicSharedMemorySize, HGB_SMEM);
    cudaFuncSetAttribute(attn2,      cudaFuncAttributeMaxDynamicSharedMemorySize, ATT2_SMEM);

    long t4;
    t4 = (long)DIM * DIM / 4;
    convert_w<<<(unsigned)((t4 + 255) / 256), 256>>>((const float4*)patch_w, (__half2*)wp, t4);
    t4 = 12L * QKVD * DIM / 4;
    convert_w<<<(unsigned)((t4 + 255) / 256), 256>>>((const float4*)qkv_w, (__half2*)wq, t4);
    t4 = 12L * DIM * DIM / 4;
    convert_w<<<(unsigned)((t4 + 255) / 256), 256>>>((const float4*)proj_w, (__half2*)wpr, t4);
    t4 = 12L * FFD * DIM / 4;
    convert_w<<<(unsigned)((t4 + 255) / 256), 256>>>((const float4*)ff1_w, (__half2*)wf1, t4);
    t4 = 12L * DIM * FFD / 4;
    convert_w<<<(unsigned)((t4 + 255) / 256), 256>>>((const float4*)ff2_w, (__half2*)wf2, t4);

    {
        int tot = PATCH_ROWS * DIM;
        im2col_split<<<(tot + 255) / 256, 256>>>(img, a16);
        hgemm<<<dim3(6, 49), 256, HG_SMEM>>>(a16, wp, DIM, patch_b, (const float*)0,
                                             tok, (__half*)0, (__half*)0, (__half*)0, (__half*)0,
                                             DIM, PATCH_ROWS, 0, 1);
        int tot2 = ROWS * DIM;
        assemble_kernel<<<(tot2 + 255) / 256, 256>>>(tok, cls_tok, pos_emb, x);
    }

    for (int l = 0; l < 12; l++) {
        ln_split_warp<<<(ROWS + 7) / 8, 256>>>(x, ln1_w + (size_t)l * DIM, ln1_b + (size_t)l * DIM, a16);
        hgemm<<<dim3(18, 50), 256, HG_SMEM>>>(a16, wq + (size_t)l * QKVD * DIM, DIM,
                                              qkv_b + (size_t)l * QKVD, (const float*)0,
                                              (float*)0, (__half*)0, q, k, v,
                                              QKVD, ROWS, 3, 0 /* single product: fp16 out masked */);
        attn2<<<BATCH * HEADS, 256, ATT2_SMEM>>>(q, k, v, a16);
        hgemm_bm64<<<dim3(6, 99), 256, HGB_SMEM>>>(a16, wpr + (size_t)l * DIM * DIM, DIM,
                                                   proj_b + (size_t)l * DIM, x,
                                                   x, DIM, ROWS, 1);
        ln_split_warp<<<(ROWS + 7) / 8, 256>>>(x, ln2_w + (size_t)l * DIM, ln2_b + (size_t)l * DIM, a16);
        hgemm<<<dim3(24, 50), 256, HG_SMEM>>>(a16, wf1 + (size_t)l * FFD * DIM, DIM,
                                              ff1_b + (size_t)l * FFD, (const float*)0,
                                              (float*)0, f16, (__half*)0, (__half*)0, (__half*)0,
                                              FFD, ROWS, 2, 1);
        hgemm_bm64<<<dim3(6, 99), 256, HGB_SMEM>>>(f16, wf2 + (size_t)l * DIM * FFD, FFD,
                                                   ff2_b + (size_t)l * DIM, x,
                                                   x, DIM, ROWS, 1);
    }

    sgemm<<<dim3(48, 1), 256>>>(x, TOK * DIM, head1_w, head1_b, hh, FFD, BATCH, FFD, DIM, 2);
    sgemm<<<dim3(16, 1), 256>>>(hh, FFD, head2_w, head2_b, out, NCLSD, BATCH, NCLSD, FFD, 0);
}

// round 14
// speedup vs baseline: 1.1844x; 1.0945x over previous
#include <cuda_runtime.h>
#include <cuda_fp16.h>
#include <math.h>
#include <stdint.h>

#define BATCH 32
#define TOK 197
#define ROWS (BATCH*TOK)
#define MPAD 6400
#define DIM 768
#define HEADS 12
#define DHD 64
#define FFD 3072
#define QKVD 2304
#define NPATCH 196
#define PATCH_ROWS (BATCH*NPATCH)
#define NCLSD 1000
#define KP2_D (2*DIM)
#define KP2_F (2*FFD)

__device__ float  g_x   [ROWS*DIM];
__device__ __align__(128) __half g_q16 [BATCH*HEADS*TOK*DHD];
__device__ __align__(128) __half g_k16 [BATCH*HEADS*TOK*DHD];
__device__ __align__(128) __half g_v16 [BATCH*HEADS*TOK*DHD];
__device__ float  g_tok [PATCH_ROWS*DIM];
__device__ float  g_hh  [BATCH*FFD];
__device__ float  g_qb  [12*QKVD];
__device__ __align__(128) __half g_a16 [MPAD*KP2_D];
__device__ __align__(128) __half g_f16 [(size_t)MPAD*KP2_F];
__device__ __align__(128) __half g_wp16  [DIM*DIM];
__device__ __align__(128) __half g_wqkv16[(size_t)12*QKVD*DIM];
__device__ __align__(128) __half g_wpr16 [(size_t)12*DIM*DIM];
__device__ __align__(128) __half g_wf1_16[(size_t)12*FFD*DIM];
__device__ __align__(128) __half g_wf2_16[(size_t)12*DIM*FFD];

__device__ __forceinline__ uint32_t smem_u32(const void* p) {
    uint32_t a;
    asm("{ .reg .u64 t; cvta.to.shared.u64 t, %1; cvt.u32.u64 %0, t; }" : "=r"(a) : "l"(p));
    return a;
}
__device__ __forceinline__ void cp_async16(uint32_t s, const void* g) {
    asm volatile("cp.async.cg.shared.global [%0], [%1], 16;\n" :: "r"(s), "l"(g));
}
#define CP_COMMIT() asm volatile("cp.async.commit_group;\n" ::: "memory")
#define CP_WAIT(n)  asm volatile("cp.async.wait_group %0;\n" :: "n"(n) : "memory")

__device__ __forceinline__ void ldsm_x4(uint32_t& r0, uint32_t& r1, uint32_t& r2, uint32_t& r3,
                                        uint32_t addr) {
    asm volatile("ldmatrix.sync.aligned.m8n8.x4.shared.b16 {%0,%1,%2,%3}, [%4];"
                 : "=r"(r0), "=r"(r1), "=r"(r2), "=r"(r3) : "r"(addr));
}
__device__ __forceinline__ void mma16816(float* c, const uint32_t* a, const uint32_t* b) {
    asm volatile("mma.sync.aligned.m16n8k16.row.col.f32.f16.f16.f32 "
        "{%0,%1,%2,%3}, {%4,%5,%6,%7}, {%8,%9}, {%0,%1,%2,%3};"
        : "+f"(c[0]), "+f"(c[1]), "+f"(c[2]), "+f"(c[3])
        : "r"(a[0]), "r"(a[1]), "r"(a[2]), "r"(a[3]), "r"(b[0]), "r"(b[1]));
}
__device__ __forceinline__ float gelu_f(float v) {
    return 0.5f * v * (1.0f + erff(v * 0.70710678118654752f));
}
__device__ __forceinline__ float wred_sum(float v) {
#pragma unroll
    for (int o = 16; o > 0; o >>= 1) v += __shfl_xor_sync(0xffffffffu, v, o);
    return v;
}

// ===== split-fp16 HMMA GEMM: BM=128 BN=128, Kc=64, 2-stage =====
// lo=1: two products; lo=0: single product.
// mode 3: QKV scatter with PERMUTED column order [Q(h,d)|K(h,d)|V(h,d)] -> half2 stores
#define STG 49152
#define HG_SMEM (2*STG)

__global__ __launch_bounds__(256, 2) void hgemm(
    const __half* __restrict__ A, const __half* __restrict__ B, int K,
    const float* __restrict__ bias, const float* __restrict__ res,
    float* __restrict__ outF, __half* __restrict__ out16,
    __half* __restrict__ gq, __half* __restrict__ gk, __half* __restrict__ gv,
    int ldc, int M, int mode, int lo)
{
    extern __shared__ char smraw[];
    uint32_t smb = smem_u32(smraw);
    int tid = threadIdx.x;
    int lane = tid & 31, wid = tid >> 5;
    int warp_m = wid & 1, warp_n = wid >> 1;
    int row0 = blockIdx.y * 128, col0 = blockIdx.x * 128;

    uint32_t ld_slot[4]; int ld_r[4], ld_c[4];
#pragma unroll
    for (int j = 0; j < 4; j++) {
        int idx = tid + j * 256;
        ld_r[j] = idx >> 3; ld_c[j] = idx & 7;
        ld_slot[j] = (uint32_t)(ld_r[j] * 128 + ((ld_c[j] ^ (ld_r[j] & 7)) << 4));
    }

    int g = lane >> 3, l = lane & 7;
    uint32_t a_roff[4], a_xor[4];
#pragma unroll
    for (int mi = 0; mi < 4; mi++) {
        int r = warp_m * 64 + mi * 16 + (g & 1) * 8 + l;
        a_roff[mi] = r * 128; a_xor[mi] = r & 7;
    }
    uint32_t b_roff[2], b_xor[2];
#pragma unroll
    for (int j2 = 0; j2 < 2; j2++) {
        int r = warp_n * 32 + j2 * 16 + (g >> 1) * 8 + l;
        b_roff[j2] = r * 128; b_xor[j2] = r & 7;
    }

    float acc[4][4][4];
#pragma unroll
    for (int mi = 0; mi < 4; mi++)
#pragma unroll
        for (int nj = 0; nj < 4; nj++)
#pragma unroll
            for (int q = 0; q < 4; q++) acc[mi][nj][q] = 0.f;

    const int KT = K >> 6;
    const size_t strA = (size_t)(2 * K);
    const size_t strB = (size_t)K;
    const __half* gA = A + (size_t)row0 * strA;
    const __half* gB = B + (size_t)col0 * strB;

#define LOAD_ST(s, kb) do { \
    uint32_t sa = smb + (uint32_t)(s) * STG; \
    _Pragma("unroll") \
    for (int j = 0; j < 4; j++) { \
        const __half* pa = gA + (size_t)ld_r[j] * strA + (size_t)(kb) * 64 + ld_c[j] * 8; \
        cp_async16(sa + ld_slot[j], pa); \
        if (lo) cp_async16(sa + 16384u + ld_slot[j], pa + K); \
        cp_async16(sa + 32768u + ld_slot[j], gB + (size_t)ld_r[j] * strB + (size_t)(kb) * 64 + ld_c[j] * 8); \
    } \
} while (0)

    LOAD_ST(0, 0); CP_COMMIT();

    for (int i = 0; i < KT; i++) {
        CP_WAIT(0);
        __syncthreads();
        if (i + 1 < KT) { LOAD_ST((i + 1) & 1, i + 1); CP_COMMIT(); }

        uint32_t ah_b = smb + (uint32_t)(i & 1) * STG;
        uint32_t al_b = ah_b + 16384u;
        uint32_t bh_b = ah_b + 32768u;
#pragma unroll
        for (int ks = 0; ks < 4; ks++) {
            uint32_t cha = (uint32_t)(ks * 2 + (g >> 1));
            uint32_t chb = (uint32_t)(ks * 2 + (g & 1));
            uint32_t afh[4][4], bf[4][2];
#pragma unroll
            for (int mi = 0; mi < 4; mi++)
                ldsm_x4(afh[mi][0], afh[mi][1], afh[mi][2], afh[mi][3],
                        ah_b + a_roff[mi] + ((cha ^ a_xor[mi]) << 4));
#pragma unroll
            for (int j2 = 0; j2 < 2; j2++)
                ldsm_x4(bf[j2 * 2][0], bf[j2 * 2][1], bf[j2 * 2 + 1][0], bf[j2 * 2 + 1][1],
                        bh_b + b_roff[j2] + ((chb ^ b_xor[j2]) << 4));
#pragma unroll
            for (int mi = 0; mi < 4; mi++)
#pragma unroll
                for (int nj = 0; nj < 4; nj++)
                    mma16816(acc[mi][nj], afh[mi], bf[nj]);
            if (lo) {
                uint32_t afl[4][4];
#pragma unroll
                for (int mi = 0; mi < 4; mi++)
                    ldsm_x4(afl[mi][0], afl[mi][1], afl[mi][2], afl[mi][3],
                            al_b + a_roff[mi] + ((cha ^ a_xor[mi]) << 4));
#pragma unroll
                for (int mi = 0; mi < 4; mi++)
#pragma unroll
                    for (int nj = 0; nj < 4; nj++)
                        mma16816(acc[mi][nj], afl[mi], bf[nj]);
            }
        }
    }

    int qrow = lane >> 2, qcol = (lane & 3) * 2;
#pragma unroll
    for (int mi = 0; mi < 4; mi++) {
        int rbase = row0 + warp_m * 64 + mi * 16 + qrow;
#pragma unroll
        for (int half = 0; half < 2; half++) {
            int r = rbase + half * 8;
            if (r >= M) continue;
            int rb = r / TOK, rn = r - rb * TOK;
#pragma unroll
            for (int nj = 0; nj < 4; nj++) {
                int c = col0 + warp_n * 32 + nj * 8 + qcol;
                float v0 = acc[mi][nj][half * 2 + 0] + __ldg(bias + c);
                float v1 = acc[mi][nj][half * 2 + 1] + __ldg(bias + c + 1);
                if (mode == 2) {
                    float g0 = gelu_f(v0), g1 = gelu_f(v1);
                    __half h0 = __float2half(g0), h1 = __float2half(g1);
                    __half l0 = __float2half(g0 - __half2float(h0));
                    __half l1 = __float2half(g1 - __half2float(h1));
                    __half* o = out16 + (size_t)r * (2 * ldc) + c;
                    *(__half2*)(o)       = __halves2half2(h0, h1);
                    *(__half2*)(o + ldc) = __halves2half2(l0, l1);
                } else if (mode == 3) {
                    // permuted columns: c = s*768 + h*64 + d (d even, d+1 same head)
                    int ss = c / 768;
                    int rem = c - ss * 768;
                    int hh = rem >> 6, dd = rem & 63;
                    __half* dst = (ss == 0) ? gq : (ss == 1) ? gk : gv;
                    *(__half2*)(dst + (((size_t)(rb * HEADS + hh)) * TOK + rn) * DHD + dd) =
                        __halves2half2(__float2half(v0), __float2half(v1));
                } else {
                    float* o = outF + (size_t)r * ldc + c;
                    if (mode == 1) {
                        const float* rr = res + (size_t)r * ldc + c;
                        v0 += rr[0]; v1 += rr[1];
                    }
                    *(float2*)o = make_float2(v0, v1);
                }
            }
        }
    }
}

// ===== hgemm_bm64: BM=64, BN=128 (tail-friendly), always two products =====
#define STGB 32768
#define HGB_SMEM (2*STGB)

__global__ __launch_bounds__(256, 2) void hgemm_bm64(
    const __half* __restrict__ A, const __half* __restrict__ B, int K,
    const float* __restrict__ bias, const float* __restrict__ res,
    float* __restrict__ outF, int ldc, int M, int mode)
{
    extern __shared__ char smraw[];
    uint32_t smb = smem_u32(smraw);
    int tid = threadIdx.x;
    int lane = tid & 31, wid = tid >> 5;
    int warp_m = wid & 1, warp_n = wid >> 1;
    int row0 = blockIdx.y * 64, col0 = blockIdx.x * 128;

    uint32_t ld_slot[4]; int ld_r[4], ld_c[4];
#pragma unroll
    for (int j = 0; j < 4; j++) {
        int idx = tid + j * 256;
        ld_r[j] = idx >> 3; ld_c[j] = idx & 7;
        ld_slot[j] = (uint32_t)(ld_r[j] * 128 + ((ld_c[j] ^ (ld_r[j] & 7)) << 4));
    }

    int g = lane >> 3, l = lane & 7;
    uint32_t a_roff[2], a_xor[2];
#pragma unroll
    for (int mi = 0; mi < 2; mi++) {
        int r = warp_m * 32 + mi * 16 + (g & 1) * 8 + l;
        a_roff[mi] = r * 128; a_xor[mi] = r & 7;
    }
    uint32_t b_roff[2], b_xor[2];
#pragma unroll
    for (int j2 = 0; j2 < 2; j2++) {
        int r = warp_n * 32 + j2 * 16 + (g >> 1) * 8 + l;
        b_roff[j2] = r * 128; b_xor[j2] = r & 7;
    }

    float acc[2][4][4];
#pragma unroll
    for (int mi = 0; mi < 2; mi++)
#pragma unroll
        for (int nj = 0; nj < 4; nj++)
#pragma unroll
            for (int q = 0; q < 4; q++) acc[mi][nj][q] = 0.f;

    const int KT = K >> 6;
    const size_t strA = (size_t)(2 * K);
    const size_t strB = (size_t)K;
    const __half* gA = A + (size_t)row0 * strA;
    const __half* gB = B + (size_t)col0 * strB;

#define LOAD_STB(s, kb) do { \
    uint32_t sa = smb + (uint32_t)(s) * STGB; \
    _Pragma("unroll") \
    for (int j = 0; j < 2; j++) { \
        const __half* pa = gA + (size_t)ld_r[j] * strA + (size_t)(kb) * 64 + ld_c[j] * 8; \
        cp_async16(sa + ld_slot[j], pa); \
        cp_async16(sa + 8192u + ld_slot[j], pa + K); \
    } \
    _Pragma("unroll") \
    for (int j = 0; j < 4; j++) { \
        cp_async16(sa + 16384u + ld_slot[j], gB + (size_t)ld_r[j] * strB + (size_t)(kb) * 64 + ld_c[j] * 8); \
    } \
} while (0)

    LOAD_STB(0, 0); CP_COMMIT();

    for (int i = 0; i < KT; i++) {
        CP_WAIT(0);
        __syncthreads();
        if (i + 1 < KT) { LOAD_STB((i + 1) & 1, i + 1); CP_COMMIT(); }

        uint32_t ah_b = smb + (uint32_t)(i & 1) * STGB;
        uint32_t al_b = ah_b + 8192u;
        uint32_t bh_b = ah_b + 16384u;
#pragma unroll
        for (int ks = 0; ks < 4; ks++) {
            uint32_t cha = (uint32_t)(ks * 2 + (g >> 1));
            uint32_t chb = (uint32_t)(ks * 2 + (g & 1));
            uint32_t afh[2][4], afl[2][4], bf[4][2];
#pragma unroll
            for (int mi = 0; mi < 2; mi++)
                ldsm_x4(afh[mi][0], afh[mi][1], afh[mi][2], afh[mi][3],
                        ah_b + a_roff[mi] + ((cha ^ a_xor[mi]) << 4));
#pragma unroll
            for (int j2 = 0; j2 < 2; j2++)
                ldsm_x4(bf[j2 * 2][0], bf[j2 * 2][1], bf[j2 * 2 + 1][0], bf[j2 * 2 + 1][1],
                        bh_b + b_roff[j2] + ((chb ^ b_xor[j2]) << 4));
#pragma unroll
            for (int mi = 0; mi < 2; mi++)
                ldsm_x4(afl[mi][0], afl[mi][1], afl[mi][2], afl[mi][3],
                        al_b + a_roff[mi] + ((cha ^ a_xor[mi]) << 4));
#pragma unroll
            for (int mi = 0; mi < 2; mi++)
#pragma unroll
                for (int nj = 0; nj < 4; nj++)
                    mma16816(acc[mi][nj], afh[mi], bf[nj]);
#pragma unroll
            for (int mi = 0; mi < 2; mi++)
#pragma unroll
                for (int nj = 0; nj < 4; nj++)
                    mma16816(acc[mi][nj], afl[mi], bf[nj]);
        }
    }

    int qrow = lane >> 2, qcol = (lane & 3) * 2;
#pragma unroll
    for (int mi = 0; mi < 2; mi++) {
        int rbase = row0 + warp_m * 32 + mi * 16 + qrow;
#pragma unroll
        for (int half = 0; half < 2; half++) {
            int r = rbase + half * 8;
            if (r >= M) continue;
#pragma unroll
            for (int nj = 0; nj < 4; nj++) {
                int c = col0 + warp_n * 32 + nj * 8 + qcol;
                float v0 = acc[mi][nj][half * 2 + 0] + __ldg(bias + c);
                float v1 = acc[mi][nj][half * 2 + 1] + __ldg(bias + c + 1);
                float* o = outF + (size_t)r * ldc + c;
                if (mode == 1) {
                    const float* rr = res + (size_t)r * ldc + c;
                    v0 += rr[0]; v1 += rr[1];
                }
                *(float2*)o = make_float2(v0, v1);
            }
        }
    }
}

// ===== helpers =====
__global__ void convert_w(const float4* __restrict__ W, __half2* __restrict__ W16, long total4)
{
    long idx = (long)blockIdx.x * blockDim.x + threadIdx.x;
    if (idx >= total4) return;
    float4 v = W[idx];
    W16[idx * 2]     = __halves2half2(__float2half(v.x), __float2half(v.y));
    W16[idx * 2 + 1] = __halves2half2(__float2half(v.z), __float2half(v.w));
}

// QKV weight convert with row permutation n_orig = h*192+d*3+s -> n_new = s*768+h*64+d
__global__ void convert_wqkv(const float4* __restrict__ W, __half2* __restrict__ W16,
                             const float* __restrict__ bsrc, float* __restrict__ bdst)
{
    const int C4 = DIM / 4;  // 192 float4 per row
    long idx = (long)blockIdx.x * blockDim.x + threadIdx.x;
    if (idx >= 12L * QKVD * C4) return;
    long row = idx / C4; int c4 = (int)(idx - row * C4);
    int lyr = (int)(row / QKVD); int n = (int)(row - (long)lyr * QKVD);
    int h = n / 192, t = n - h * 192, d = t / 3, s = t - d * 3;
    int n_new = s * 768 + h * 64 + d;
    float4 v = W[idx];
    __half2* dst = W16 + (((size_t)lyr * QKVD + n_new) * DIM + c4 * 4) / 2;
    dst[0] = __halves2half2(__float2half(v.x), __float2half(v.y));
    dst[1] = __halves2half2(__float2half(v.z), __float2half(v.w));
    if (c4 == 0) bdst[(size_t)lyr * QKVD + n_new] = bsrc[(size_t)lyr * QKVD + n];
}

__global__ __launch_bounds__(256) void ln_split_warp(
    const float* __restrict__ x, const float* __restrict__ w,
    const float* __restrict__ b, __half* __restrict__ y16)
{
    int row = blockIdx.x * 8 + (threadIdx.x >> 5);
    if (row >= ROWS) return;
    int lane = threadIdx.x & 31;
    const float4* xr = (const float4*)(x + (size_t)row * DIM);
    float4 vx[6];
    float s = 0.f;
#pragma unroll
    for (int i = 0; i < 6; i++) {
        vx[i] = xr[lane + 32 * i];
        s += (vx[i].x + vx[i].y) + (vx[i].z + vx[i].w);
    }
    s = wred_sum(s);
    float mean = s * (1.0f / 768.f);
    float s2 = 0.f;
#pragma unroll
    for (int i = 0; i < 6; i++) {
        float a0 = vx[i].x - mean, a1 = vx[i].y - mean;
        float a2 = vx[i].z - mean, a3 = vx[i].w - mean;
        s2 += a0 * a0 + a1 * a1 + a2 * a2 + a3 * a3;
    }
    s2 = wred_sum(s2);
    float inv = rsqrtf(s2 * (1.0f / 768.f) + 1e-5f);
    const float4* wr = (const float4*)w;
    const float4* br = (const float4*)b;
    __half2* yh = (__half2*)(y16 + (size_t)row * KP2_D);
    __half2* yl = (__half2*)(y16 + (size_t)row * KP2_D + DIM);
#pragma unroll
    for (int i = 0; i < 6; i++) {
        int c4 = lane + 32 * i;
        float4 w4 = wr[c4], b4 = br[c4];
        float v0 = (vx[i].x - mean) * inv * w4.x + b4.x;
        float v1 = (vx[i].y - mean) * inv * w4.y + b4.y;
        float v2 = (vx[i].z - mean) * inv * w4.z + b4.z;
        float v3 = (vx[i].w - mean) * inv * w4.w + b4.w;
        __half h0 = __float2half(v0), h1 = __float2half(v1);
        __half h2 = __float2half(v2), h3 = __float2half(v3);
        yh[c4 * 2]     = __halves2half2(h0, h1);
        yh[c4 * 2 + 1] = __halves2half2(h2, h3);
        yl[c4 * 2]     = __halves2half2(__float2half(v0 - __half2float(h0)),
                                        __float2half(v1 - __half2float(h1)));
        yl[c4 * 2 + 1] = __halves2half2(__float2half(v2 - __half2float(h2)),
                                        __float2half(v3 - __half2float(h3)));
    }
}

__global__ void im2col_split(const float* __restrict__ img, __half* __restrict__ a16)
{
    int idx = blockIdx.x * blockDim.x + threadIdx.x;
    if (idx >= PATCH_ROWS * DIM) return;
    int e = idx % DIM;
    int m = idx / DIM;
    int b = m / NPATCH, p = m % NPATCH;
    int gr = p / 14, gc = p % 14;
    int c = e % 3;
    int pp = e / 3;
    int pr = pp / 16, pc = pp % 16;
    float v = img[(((size_t)b * 3 + c) * 224 + gr * 16 + pr) * 224 + gc * 16 + pc];
    __half hi = __float2half(v);
    __half* dst = a16 + (size_t)m * KP2_D;
    dst[e] = hi;
    dst[DIM + e] = __float2half(v - __half2float(hi));
}

__global__ void assemble_kernel(const float* __restrict__ tokens,
                                const float* __restrict__ cls,
                                const float* __restrict__ pos,
                                float* __restrict__ x)
{
    int idx = blockIdx.x * blockDim.x + threadIdx.x;
    if (idx >= ROWS * DIM) return;
    int d = idx % DIM;
    int r = idx / DIM;
    int b = r / TOK, n = r % TOK;
    float v = (n == 0) ? cls[d] : tokens[((size_t)b * NPATCH + (n - 1)) * DIM + d];
    x[idx] = v + pos[(size_t)n * DIM + d];
}

// ===== attention: 2 queries per warp, fp16 K/V in smem =====
#define ATT_PAD 33
#define ATT2_SMEM ((2*TOK*ATT_PAD + 16*ATT_PAD) * 4 + 16*200*4)

__global__ __launch_bounds__(256) void attn2(
    const __half* __restrict__ Q, const __half* __restrict__ K,
    const __half* __restrict__ V, __half* __restrict__ a16)
{
    extern __shared__ char smraw[];
    __half2* ks2 = (__half2*)smraw;
    __half2* vs2 = ks2 + TOK * ATT_PAD;
    __half2* qs2 = vs2 + TOK * ATT_PAD;
    float*   sc  = (float*)(qs2 + 16 * ATT_PAD);

    int bh = blockIdx.x;
    int b = bh / HEADS, h = bh % HEADS;
    int tid = threadIdx.x, lane = tid & 31, w = tid >> 5;
    const __half2* Qb = (const __half2*)(Q + (size_t)bh * TOK * DHD);
    const __half2* Kb = (const __half2*)(K + (size_t)bh * TOK * DHD);
    const __half2* Vb = (const __half2*)(V + (size_t)bh * TOK * DHD);

    for (int i = tid; i < TOK * 32; i += 256) {
        int n = i >> 5, d2 = i & 31;
        ks2[n * ATT_PAD + d2] = Kb[i];
        vs2[n * ATT_PAD + d2] = Vb[i];
    }
    __syncthreads();

    float* scw0 = sc + w * 400;
    float* scw1 = scw0 + 200;
    __half2* q0 = qs2 + (w * 2) * ATT_PAD;
    __half2* q1 = q0 + ATT_PAD;

    for (int base = 0; base < TOK; base += 16) {
        int nq0 = base + w * 2, nq1 = nq0 + 1;
        bool ok0 = (nq0 < TOK), ok1 = (nq1 < TOK);
        if (ok0) q0[lane] = Qb[(size_t)nq0 * 32 + lane];
        if (ok1) q1[lane] = Qb[(size_t)nq1 * 32 + lane];
        __syncwarp();
        if (!ok0) { continue; }
        float mx0 = -1e30f, mx1 = -1e30f;
        for (int kk = lane; kk < TOK; kk += 32) {
            float s0 = 0.f, s1 = 0.f;
#pragma unroll
            for (int d2 = 0; d2 < 32; d2++) {
                float2 kv  = __half22float2(ks2[kk * ATT_PAD + d2]);
                float2 qv0 = __half22float2(q0[d2]);
                float2 qv1 = __half22float2(q1[d2]);
                s0 += kv.x * qv0.x + kv.y * qv0.y;
                s1 += kv.x * qv1.x + kv.y * qv1.y;
            }
            scw0[kk] = s0 * 0.125f;
            scw1[kk] = s1 * 0.125f;
            mx0 = fmaxf(mx0, s0 * 0.125f);
            mx1 = fmaxf(mx1, s1 * 0.125f);
        }
#pragma unroll
        for (int o = 16; o > 0; o >>= 1) {
            mx0 = fmaxf(mx0, __shfl_xor_sync(0xffffffffu, mx0, o));
            mx1 = fmaxf(mx1, __shfl_xor_sync(0xffffffffu, mx1, o));
        }
        float sum0 = 0.f, sum1 = 0.f;
        for (int kk = lane; kk < TOK; kk += 32) {
            float p0 = expf(scw0[kk] - mx0);
            float p1 = expf(scw1[kk] - mx1);
            scw0[kk] = p0; scw1[kk] = p1;
            sum0 += p0; sum1 += p1;
        }
        sum0 = wred_sum(sum0); sum1 = wred_sum(sum1);
        float inv0 = 1.f / sum0, inv1 = 1.f / sum1;
        __syncwarp();
        float ax0 = 0.f, ay0 = 0.f, ax1 = 0.f, ay1 = 0.f;
        for (int kk = 0; kk < TOK; kk++) {
            float2 vv = __half22float2(vs2[kk * ATT_PAD + lane]);
            float p0 = scw0[kk], p1 = scw1[kk];
            ax0 += p0 * vv.x; ay0 += p0 * vv.y;
            ax1 += p1 * vv.x; ay1 += p1 * vv.y;
        }
        ax0 *= inv0; ay0 *= inv0; ax1 *= inv1; ay1 *= inv1;
        {
            size_t o0 = ((size_t)(b * TOK + nq0)) * KP2_D + h * DHD + lane * 2;
            __half h0 = __float2half(ax0), h1 = __float2half(ay0);
            a16[o0] = h0; a16[o0 + 1] = h1;
            a16[o0 + DIM]     = __float2half(ax0 - __half2float(h0));
            a16[o0 + DIM + 1] = __float2half(ay0 - __half2float(h1));
        }
        if (ok1) {
            size_t o1 = ((size_t)(b * TOK + nq1)) * KP2_D + h * DHD + lane * 2;
            __half h0 = __float2half(ax1), h1 = __float2half(ay1);
            a16[o1] = h0; a16[o1 + 1] = h1;
            a16[o1 + DIM]     = __float2half(ax1 - __half2float(h0));
            a16[o1 + DIM + 1] = __float2half(ay1 - __half2float(h1));
        }
        __syncwarp();
    }
}

// fp32 SGEMM for the tiny head (M=32)
__global__ __launch_bounds__(256) void sgemm(
    const float* __restrict__ A, int lda,
    const float* __restrict__ W, const float* __restrict__ bias,
    float* __restrict__ C, int ldc, int M, int N, int K, int act)
{
    __shared__ float As[16][128];
    __shared__ float Bs[16][64];
    int tid = threadIdx.x;
    int tx = tid & 15, ty = tid >> 4;
    int row0 = blockIdx.y * 128;
    int col0 = blockIdx.x * 64;
    float acc[8][4];
#pragma unroll
    for (int i = 0; i < 8; i++)
#pragma unroll
        for (int j = 0; j < 4; j++) acc[i][j] = 0.f;
    for (int k0 = 0; k0 < K; k0 += 16) {
#pragma unroll
        for (int i = 0; i < 2; i++) {
            int idx = tid + i * 256;
            int r = idx >> 2, c = (idx & 3) << 2;
            int gr = row0 + r;
            float4 v = make_float4(0.f, 0.f, 0.f, 0.f);
            if (gr < M) v = *(const float4*)(A + (size_t)gr * lda + k0 + c);
            As[c + 0][r] = v.x; As[c + 1][r] = v.y; As[c + 2][r] = v.z; As[c + 3][r] = v.w;
        }
        {
            int n = tid >> 2, c = (tid & 3) << 2;
            int gn = col0 + n;
            float4 v = make_float4(0.f, 0.f, 0.f, 0.f);
            if (gn < N) v = *(const float4*)(W + (size_t)gn * K + k0 + c);
            Bs[c + 0][n] = v.x; Bs[c + 1][n] = v.y; Bs[c + 2][n] = v.z; Bs[c + 3][n] = v.w;
        }
        __syncthreads();
#pragma unroll
        for (int kk = 0; kk < 16; kk++) {
            float4 a0 = *(const float4*)&As[kk][ty * 8];
            float4 a1 = *(const float4*)&As[kk][ty * 8 + 4];
            float4 bb = *(const float4*)&Bs[kk][tx * 4];
            float av[8] = {a0.x, a0.y, a0.z, a0.w, a1.x, a1.y, a1.z, a1.w};
            float bv[4] = {bb.x, bb.y, bb.z, bb.w};
#pragma unroll
            for (int i = 0; i < 8; i++)
#pragma unroll
                for (int j = 0; j < 4; j++) acc[i][j] += av[i] * bv[j];
        }
        __syncthreads();
    }
#pragma unroll
    for (int i = 0; i < 8; i++) {
        int gr = row0 + ty * 8 + i;
        if (gr >= M) continue;
#pragma unroll
        for (int j = 0; j < 4; j++) {
            int gn = col0 + tx * 4 + j;
            if (gn >= N) continue;
            float v = acc[i][j];
            if (bias) v += bias[gn];
            if (act == 2) v = tanhf(v);
            C[(size_t)gr * ldc + gn] = v;
        }
    }
}

extern "C" void kernel_launch(void* const* d_in, const int* in_sizes, int n_in,
                              void* d_out, int out_size)
{
    const float* img     = (const float*)d_in[0];
    const float* patch_w = (const float*)d_in[1];
    const float* patch_b = (const float*)d_in[2];
    const float* cls_tok = (const float*)d_in[3];
    const float* pos_emb = (const float*)d_in[4];
    const float* ln1_w   = (const float*)d_in[5];
    const float* ln1_b   = (const float*)d_in[6];
    const float* qkv_w   = (const float*)d_in[7];
    const float* qkv_b   = (const float*)d_in[8];
    const float* proj_w  = (const float*)d_in[9];
    const float* proj_b  = (const float*)d_in[10];
    const float* ln2_w   = (const float*)d_in[11];
    const float* ln2_b   = (const float*)d_in[12];
    const float* ff1_w   = (const float*)d_in[13];
    const float* ff1_b   = (const float*)d_in[14];
    const float* ff2_w   = (const float*)d_in[15];
    const float* ff2_b   = (const float*)d_in[16];
    const float* head1_w = (const float*)d_in[17];
    const float* head1_b = (const float*)d_in[18];
    const float* head2_w = (const float*)d_in[19];
    const float* head2_b = (const float*)d_in[20];
    float* out = (float*)d_out;

    float *x, *tok, *hh, *qb;
    __half *q, *k, *v, *a16, *f16, *wp, *wq, *wpr, *wf1, *wf2;
    cudaGetSymbolAddress((void**)&x,   g_x);
    cudaGetSymbolAddress((void**)&q,   g_q16);
    cudaGetSymbolAddress((void**)&k,   g_k16);
    cudaGetSymbolAddress((void**)&v,   g_v16);
    cudaGetSymbolAddress((void**)&tok, g_tok);
    cudaGetSymbolAddress((void**)&hh,  g_hh);
    cudaGetSymbolAddress((void**)&qb,  g_qb);
    cudaGetSymbolAddress((void**)&a16, g_a16);
    cudaGetSymbolAddress((void**)&f16, g_f16);
    cudaGetSymbolAddress((void**)&wp,  g_wp16);
    cudaGetSymbolAddress((void**)&wq,  g_wqkv16);
    cudaGetSymbolAddress((void**)&wpr, g_wpr16);
    cudaGetSymbolAddress((void**)&wf1, g_wf1_16);
    cudaGetSymbolAddress((void**)&wf2, g_wf2_16);

    cudaFuncSetAttribute(hgemm,      cudaFuncAttributeMaxDynamicSharedMemorySize, HG_SMEM);
    cudaFuncSetAttribute(hgemm_bm64, cudaFuncAttributeMaxDynamicSharedMemorySize, HGB_SMEM);
    cudaFuncSetAttribute(attn2,      cudaFuncAttributeMaxDynamicSharedMemorySize, ATT2_SMEM);

    long t4;
    t4 = (long)DIM * DIM / 4;
    convert_w<<<(unsigned)((t4 + 255) / 256), 256>>>((const float4*)patch_w, (__half2*)wp, t4);
    t4 = 12L * QKVD * DIM / 4;
    convert_wqkv<<<(unsigned)((t4 + 255) / 256), 256>>>((const float4*)qkv_w, (__half2*)wq,
                                                        qkv_b, qb);
    t4 = 12L * DIM * DIM / 4;
    convert_w<<<(unsigned)((t4 + 255) / 256), 256>>>((const float4*)proj_w, (__half2*)wpr, t4);
    t4 = 12L * FFD * DIM / 4;
    convert_w<<<(unsigned)((t4 + 255) / 256), 256>>>((const float4*)ff1_w, (__half2*)wf1, t4);
    t4 = 12L * DIM * FFD / 4;
    convert_w<<<(unsigned)((t4 + 255) / 256), 256>>>((const float4*)ff2_w, (__half2*)wf2, t4);

    {
        int tot = PATCH_ROWS * DIM;
        im2col_split<<<(tot + 255) / 256, 256>>>(img, a16);
        hgemm<<<dim3(6, 49), 256, HG_SMEM>>>(a16, wp, DIM, patch_b, (const float*)0,
                                             tok, (__half*)0, (__half*)0, (__half*)0, (__half*)0,
                                             DIM, PATCH_ROWS, 0, 1);
        int tot2 = ROWS * DIM;
        assemble_kernel<<<(tot2 + 255) / 256, 256>>>(tok, cls_tok, pos_emb, x);
    }

    for (int l = 0; l < 12; l++) {
        ln_split_warp<<<(ROWS + 7) / 8, 256>>>(x, ln1_w + (size_t)l * DIM, ln1_b + (size_t)l * DIM, a16);
        hgemm<<<dim3(18, 50), 256, HG_SMEM>>>(a16, wq + (size_t)l * QKVD * DIM, DIM,
                                              qb + (size_t)l * QKVD, (const float*)0,
                                              (float*)0, (__half*)0, q, k, v,
                                              QKVD, ROWS, 3, 0);
        attn2<<<BATCH * HEADS, 256, ATT2_SMEM>>>(q, k, v, a16);
        hgemm_bm64<<<dim3(6, 99), 256, HGB_SMEM>>>(a16, wpr + (size_t)l * DIM * DIM, DIM,
                                                   proj_b + (size_t)l * DIM, x,
                                                   x, DIM, ROWS, 1);
        ln_split_warp<<<(ROWS + 7) / 8, 256>>>(x, ln2_w + (size_t)l * DIM, ln2_b + (size_t)l * DIM, a16);
        hgemm<<<dim3(24, 50), 256, HG_SMEM>>>(a16, wf1 + (size_t)l * FFD * DIM, DIM,
                                              ff1_b + (size_t)l * FFD, (const float*)0,
                                              (float*)0, f16, (__half*)0, (__half*)0, (__half*)0,
                                              FFD, ROWS, 2, 1);
        hgemm_bm64<<<dim3(6, 99), 256, HGB_SMEM>>>(f16, wf2 + (size_t)l * DIM * FFD, FFD,
                                                   ff2_b + (size_t)l * DIM, x,
                                                   x, DIM, ROWS, 1);
    }

    sgemm<<<dim3(48, 1), 256>>>(x, TOK * DIM, head1_w, head1_b, hh, FFD, BATCH, FFD, DIM, 2);
    sgemm<<<dim3(16, 1), 256>>>(hh, FFD, head2_w, head2_b, out, NCLSD, BATCH, NCLSD, FFD, 0);
}

// round 15
// speedup vs baseline: 1.2789x; 1.0798x over previous
#include <cuda_runtime.h>
#include <cuda_fp16.h>
#include <math.h>
#include <stdint.h>

#define BATCH 32
#define TOK 197
#define ROWS (BATCH*TOK)
#define MPAD 6400
#define DIM 768
#define HEADS 12
#define DHD 64
#define FFD 3072
#define QKVD 2304
#define NPATCH 196
#define PATCH_ROWS (BATCH*NPATCH)
#define NCLSD 1000
#define KP2_D (2*DIM)
#define KP2_F (2*FFD)

__device__ float  g_x   [ROWS*DIM];
__device__ __align__(128) __half g_q16 [BATCH*HEADS*TOK*DHD];
__device__ __align__(128) __half g_k16 [BATCH*HEADS*TOK*DHD];
__device__ __align__(128) __half g_v16 [BATCH*HEADS*TOK*DHD];
__device__ float  g_tok [PATCH_ROWS*DIM];
__device__ float  g_hh  [BATCH*FFD];
__device__ float  g_qb  [12*QKVD];
__device__ __align__(128) __half g_a16 [MPAD*KP2_D];
__device__ __align__(128) __half g_f16 [(size_t)MPAD*KP2_F];
__device__ __align__(128) __half g_wp16  [DIM*DIM];
__device__ __align__(128) __half g_wqkv16[(size_t)12*QKVD*DIM];
__device__ __align__(128) __half g_wpr16 [(size_t)12*DIM*DIM];
__device__ __align__(128) __half g_wf1_16[(size_t)12*FFD*DIM];
__device__ __align__(128) __half g_wf2_16[(size_t)12*DIM*FFD];

__device__ __forceinline__ uint32_t smem_u32(const void* p) {
    uint32_t a;
    asm("{ .reg .u64 t; cvta.to.shared.u64 t, %1; cvt.u32.u64 %0, t; }" : "=r"(a) : "l"(p));
    return a;
}
__device__ __forceinline__ void cp_async16(uint32_t s, const void* g) {
    asm volatile("cp.async.cg.shared.global [%0], [%1], 16;\n" :: "r"(s), "l"(g));
}
#define CP_COMMIT() asm volatile("cp.async.commit_group;\n" ::: "memory")
#define CP_WAIT(n)  asm volatile("cp.async.wait_group %0;\n" :: "n"(n) : "memory")

__device__ __forceinline__ void ldsm_x4(uint32_t& r0, uint32_t& r1, uint32_t& r2, uint32_t& r3,
                                        uint32_t addr) {
    asm volatile("ldmatrix.sync.aligned.m8n8.x4.shared.b16 {%0,%1,%2,%3}, [%4];"
                 : "=r"(r0), "=r"(r1), "=r"(r2), "=r"(r3) : "r"(addr));
}
__device__ __forceinline__ void mma16816(float* c, const uint32_t* a, const uint32_t* b) {
    asm volatile("mma.sync.aligned.m16n8k16.row.col.f32.f16.f16.f32 "
        "{%0,%1,%2,%3}, {%4,%5,%6,%7}, {%8,%9}, {%0,%1,%2,%3};"
        : "+f"(c[0]), "+f"(c[1]), "+f"(c[2]), "+f"(c[3])
        : "r"(a[0]), "r"(a[1]), "r"(a[2]), "r"(a[3]), "r"(b[0]), "r"(b[1]));
}
__device__ __forceinline__ float gelu_f(float v) {
    return 0.5f * v * (1.0f + erff(v * 0.70710678118654752f));
}
__device__ __forceinline__ float wred_sum(float v) {
#pragma unroll
    for (int o = 16; o > 0; o >>= 1) v += __shfl_xor_sync(0xffffffffu, v, o);
    return v;
}

// ===== split-fp16 HMMA GEMM: BM=128 BN=128, Kc=64, 2-stage =====
// lo=1: two products; lo=0: single product.
// mode 3: QKV scatter with PERMUTED column order [Q(h,d)|K(h,d)|V(h,d)] -> half2 stores
#define STG 49152
#define HG_SMEM (2*STG)

__global__ __launch_bounds__(256, 2) void hgemm(
    const __half* __restrict__ A, const __half* __restrict__ B, int K,
    const float* __restrict__ bias, const float* __restrict__ res,
    float* __restrict__ outF, __half* __restrict__ out16,
    __half* __restrict__ gq, __half* __restrict__ gk, __half* __restrict__ gv,
    int ldc, int M, int mode, int lo)
{
    extern __shared__ char smraw[];
    uint32_t smb = smem_u32(smraw);
    int tid = threadIdx.x;
    int lane = tid & 31, wid = tid >> 5;
    int warp_m = wid & 1, warp_n = wid >> 1;
    int row0 = blockIdx.y * 128, col0 = blockIdx.x * 128;

    uint32_t ld_slot[4]; int ld_r[4], ld_c[4];
#pragma unroll
    for (int j = 0; j < 4; j++) {
        int idx = tid + j * 256;
        ld_r[j] = idx >> 3; ld_c[j] = idx & 7;
        ld_slot[j] = (uint32_t)(ld_r[j] * 128 + ((ld_c[j] ^ (ld_r[j] & 7)) << 4));
    }

    int g = lane >> 3, l = lane & 7;
    uint32_t a_roff[4], a_xor[4];
#pragma unroll
    for (int mi = 0; mi < 4; mi++) {
        int r = warp_m * 64 + mi * 16 + (g & 1) * 8 + l;
        a_roff[mi] = r * 128; a_xor[mi] = r & 7;
    }
    uint32_t b_roff[2], b_xor[2];
#pragma unroll
    for (int j2 = 0; j2 < 2; j2++) {
        int r = warp_n * 32 + j2 * 16 + (g >> 1) * 8 + l;
        b_roff[j2] = r * 128; b_xor[j2] = r & 7;
    }

    float acc[4][4][4];
#pragma unroll
    for (int mi = 0; mi < 4; mi++)
#pragma unroll
        for (int nj = 0; nj < 4; nj++)
#pragma unroll
            for (int q = 0; q < 4; q++) acc[mi][nj][q] = 0.f;

    const int KT = K >> 6;
    const size_t strA = (size_t)(2 * K);
    const size_t strB = (size_t)K;
    const __half* gA = A + (size_t)row0 * strA;
    const __half* gB = B + (size_t)col0 * strB;

#define LOAD_ST(s, kb) do { \
    uint32_t sa = smb + (uint32_t)(s) * STG; \
    _Pragma("unroll") \
    for (int j = 0; j < 4; j++) { \
        const __half* pa = gA + (size_t)ld_r[j] * strA + (size_t)(kb) * 64 + ld_c[j] * 8; \
        cp_async16(sa + ld_slot[j], pa); \
        if (lo) cp_async16(sa + 16384u + ld_slot[j], pa + K); \
        cp_async16(sa + 32768u + ld_slot[j], gB + (size_t)ld_r[j] * strB + (size_t)(kb) * 64 + ld_c[j] * 8); \
    } \
} while (0)

    LOAD_ST(0, 0); CP_COMMIT();

    for (int i = 0; i < KT; i++) {
        CP_WAIT(0);
        __syncthreads();
        if (i + 1 < KT) { LOAD_ST((i + 1) & 1, i + 1); CP_COMMIT(); }

        uint32_t ah_b = smb + (uint32_t)(i & 1) * STG;
        uint32_t al_b = ah_b + 16384u;
        uint32_t bh_b = ah_b + 32768u;
#pragma unroll
        for (int ks = 0; ks < 4; ks++) {
            uint32_t cha = (uint32_t)(ks * 2 + (g >> 1));
            uint32_t chb = (uint32_t)(ks * 2 + (g & 1));
            uint32_t afh[4][4], bf[4][2];
#pragma unroll
            for (int mi = 0; mi < 4; mi++)
                ldsm_x4(afh[mi][0], afh[mi][1], afh[mi][2], afh[mi][3],
                        ah_b + a_roff[mi] + ((cha ^ a_xor[mi]) << 4));
#pragma unroll
            for (int j2 = 0; j2 < 2; j2++)
                ldsm_x4(bf[j2 * 2][0], bf[j2 * 2][1], bf[j2 * 2 + 1][0], bf[j2 * 2 + 1][1],
                        bh_b + b_roff[j2] + ((chb ^ b_xor[j2]) << 4));
#pragma unroll
            for (int mi = 0; mi < 4; mi++)
#pragma unroll
                for (int nj = 0; nj < 4; nj++)
                    mma16816(acc[mi][nj], afh[mi], bf[nj]);
            if (lo) {
                uint32_t afl[4][4];
#pragma unroll
                for (int mi = 0; mi < 4; mi++)
                    ldsm_x4(afl[mi][0], afl[mi][1], afl[mi][2], afl[mi][3],
                            al_b + a_roff[mi] + ((cha ^ a_xor[mi]) << 4));
#pragma unroll
                for (int mi = 0; mi < 4; mi++)
#pragma unroll
                    for (int nj = 0; nj < 4; nj++)
                        mma16816(acc[mi][nj], afl[mi], bf[nj]);
            }
        }
    }

    int qrow = lane >> 2, qcol = (lane & 3) * 2;
#pragma unroll
    for (int mi = 0; mi < 4; mi++) {
        int rbase = row0 + warp_m * 64 + mi * 16 + qrow;
#pragma unroll
        for (int half = 0; half < 2; half++) {
            int r = rbase + half * 8;
            if (r >= M) continue;
            int rb = r / TOK, rn = r - rb * TOK;
#pragma unroll
            for (int nj = 0; nj < 4; nj++) {
                int c = col0 + warp_n * 32 + nj * 8 + qcol;
                float v0 = acc[mi][nj][half * 2 + 0] + __ldg(bias + c);
                float v1 = acc[mi][nj][half * 2 + 1] + __ldg(bias + c + 1);
                if (mode == 2) {
                    float g0 = gelu_f(v0), g1 = gelu_f(v1);
                    __half h0 = __float2half(g0), h1 = __float2half(g1);
                    __half l0 = __float2half(g0 - __half2float(h0));
                    __half l1 = __float2half(g1 - __half2float(h1));
                    __half* o = out16 + (size_t)r * (2 * ldc) + c;
                    *(__half2*)(o)       = __halves2half2(h0, h1);
                    *(__half2*)(o + ldc) = __halves2half2(l0, l1);
                } else if (mode == 3) {
                    int ss = c / 768;
                    int rem = c - ss * 768;
                    int hh = rem >> 6, dd = rem & 63;
                    __half* dst = (ss == 0) ? gq : (ss == 1) ? gk : gv;
                    *(__half2*)(dst + (((size_t)(rb * HEADS + hh)) * TOK + rn) * DHD + dd) =
                        __halves2half2(__float2half(v0), __float2half(v1));
                } else {
                    float* o = outF + (size_t)r * ldc + c;
                    if (mode == 1) {
                        const float* rr = res + (size_t)r * ldc + c;
                        v0 += rr[0]; v1 += rr[1];
                    }
                    *(float2*)o = make_float2(v0, v1);
                }
            }
        }
    }
}

// ===== hgemm_bm64: BM=64, BN=128 (tail-friendly), always two products =====
#define STGB 32768
#define HGB_SMEM (2*STGB)

__global__ __launch_bounds__(256, 2) void hgemm_bm64(
    const __half* __restrict__ A, const __half* __restrict__ B, int K,
    const float* __restrict__ bias, const float* __restrict__ res,
    float* __restrict__ outF, int ldc, int M, int mode)
{
    extern __shared__ char smraw[];
    uint32_t smb = smem_u32(smraw);
    int tid = threadIdx.x;
    int lane = tid & 31, wid = tid >> 5;
    int warp_m = wid & 1, warp_n = wid >> 1;
    int row0 = blockIdx.y * 64, col0 = blockIdx.x * 128;

    uint32_t ld_slot[4]; int ld_r[4], ld_c[4];
#pragma unroll
    for (int j = 0; j < 4; j++) {
        int idx = tid + j * 256;
        ld_r[j] = idx >> 3; ld_c[j] = idx & 7;
        ld_slot[j] = (uint32_t)(ld_r[j] * 128 + ((ld_c[j] ^ (ld_r[j] & 7)) << 4));
    }

    int g = lane >> 3, l = lane & 7;
    uint32_t a_roff[2], a_xor[2];
#pragma unroll
    for (int mi = 0; mi < 2; mi++) {
        int r = warp_m * 32 + mi * 16 + (g & 1) * 8 + l;
        a_roff[mi] = r * 128; a_xor[mi] = r & 7;
    }
    uint32_t b_roff[2], b_xor[2];
#pragma unroll
    for (int j2 = 0; j2 < 2; j2++) {
        int r = warp_n * 32 + j2 * 16 + (g >> 1) * 8 + l;
        b_roff[j2] = r * 128; b_xor[j2] = r & 7;
    }

    float acc[2][4][4];
#pragma unroll
    for (int mi = 0; mi < 2; mi++)
#pragma unroll
        for (int nj = 0; nj < 4; nj++)
#pragma unroll
            for (int q = 0; q < 4; q++) acc[mi][nj][q] = 0.f;

    const int KT = K >> 6;
    const size_t strA = (size_t)(2 * K);
    const size_t strB = (size_t)K;
    const __half* gA = A + (size_t)row0 * strA;
    const __half* gB = B + (size_t)col0 * strB;

#define LOAD_STB(s, kb) do { \
    uint32_t sa = smb + (uint32_t)(s) * STGB; \
    _Pragma("unroll") \
    for (int j = 0; j < 2; j++) { \
        const __half* pa = gA + (size_t)ld_r[j] * strA + (size_t)(kb) * 64 + ld_c[j] * 8; \
        cp_async16(sa + ld_slot[j], pa); \
        cp_async16(sa + 8192u + ld_slot[j], pa + K); \
    } \
    _Pragma("unroll") \
    for (int j = 0; j < 4; j++) { \
        cp_async16(sa + 16384u + ld_slot[j], gB + (size_t)ld_r[j] * strB + (size_t)(kb) * 64 + ld_c[j] * 8); \
    } \
} while (0)

    LOAD_STB(0, 0); CP_COMMIT();

    for (int i = 0; i < KT; i++) {
        CP_WAIT(0);
        __syncthreads();
        if (i + 1 < KT) { LOAD_STB((i + 1) & 1, i + 1); CP_COMMIT(); }

        uint32_t ah_b = smb + (uint32_t)(i & 1) * STGB;
        uint32_t al_b = ah_b + 8192u;
        uint32_t bh_b = ah_b + 16384u;
#pragma unroll
        for (int ks = 0; ks < 4; ks++) {
            uint32_t cha = (uint32_t)(ks * 2 + (g >> 1));
            uint32_t chb = (uint32_t)(ks * 2 + (g & 1));
            uint32_t afh[2][4], afl[2][4], bf[4][2];
#pragma unroll
            for (int mi = 0; mi < 2; mi++)
                ldsm_x4(afh[mi][0], afh[mi][1], afh[mi][2], afh[mi][3],
                        ah_b + a_roff[mi] + ((cha ^ a_xor[mi]) << 4));
#pragma unroll
            for (int j2 = 0; j2 < 2; j2++)
                ldsm_x4(bf[j2 * 2][0], bf[j2 * 2][1], bf[j2 * 2 + 1][0], bf[j2 * 2 + 1][1],
                        bh_b + b_roff[j2] + ((chb ^ b_xor[j2]) << 4));
#pragma unroll
            for (int mi = 0; mi < 2; mi++)
                ldsm_x4(afl[mi][0], afl[mi][1], afl[mi][2], afl[mi][3],
                        al_b + a_roff[mi] + ((cha ^ a_xor[mi]) << 4));
#pragma unroll
            for (int mi = 0; mi < 2; mi++)
#pragma unroll
                for (int nj = 0; nj < 4; nj++)
                    mma16816(acc[mi][nj], afh[mi], bf[nj]);
#pragma unroll
            for (int mi = 0; mi < 2; mi++)
#pragma unroll
                for (int nj = 0; nj < 4; nj++)
                    mma16816(acc[mi][nj], afl[mi], bf[nj]);
        }
    }

    int qrow = lane >> 2, qcol = (lane & 3) * 2;
#pragma unroll
    for (int mi = 0; mi < 2; mi++) {
        int rbase = row0 + warp_m * 32 + mi * 16 + qrow;
#pragma unroll
        for (int half = 0; half < 2; half++) {
            int r = rbase + half * 8;
            if (r >= M) continue;
#pragma unroll
            for (int nj = 0; nj < 4; nj++) {
                int c = col0 + warp_n * 32 + nj * 8 + qcol;
                float v0 = acc[mi][nj][half * 2 + 0] + __ldg(bias + c);
                float v1 = acc[mi][nj][half * 2 + 1] + __ldg(bias + c + 1);
                float* o = outF + (size_t)r * ldc + c;
                if (mode == 1) {
                    const float* rr = res + (size_t)r * ldc + c;
                    v0 += rr[0]; v1 += rr[1];
                }
                *(float2*)o = make_float2(v0, v1);
            }
        }
    }
}

// ===== helpers =====
__global__ void convert_w(const float4* __restrict__ W, __half2* __restrict__ W16, long total4)
{
    long idx = (long)blockIdx.x * blockDim.x + threadIdx.x;
    if (idx >= total4) return;
    float4 v = W[idx];
    W16[idx * 2]     = __halves2half2(__float2half(v.x), __float2half(v.y));
    W16[idx * 2 + 1] = __halves2half2(__float2half(v.z), __float2half(v.w));
}

// QKV weight convert with row permutation n_orig = h*192+d*3+s -> n_new = s*768+h*64+d
__global__ void convert_wqkv(const float4* __restrict__ W, __half2* __restrict__ W16,
                             const float* __restrict__ bsrc, float* __restrict__ bdst)
{
    const int C4 = DIM / 4;
    long idx = (long)blockIdx.x * blockDim.x + threadIdx.x;
    if (idx >= 12L * QKVD * C4) return;
    long row = idx / C4; int c4 = (int)(idx - row * C4);
    int lyr = (int)(row / QKVD); int n = (int)(row - (long)lyr * QKVD);
    int h = n / 192, t = n - h * 192, d = t / 3, s = t - d * 3;
    int n_new = s * 768 + h * 64 + d;
    float4 v = W[idx];
    __half2* dst = W16 + (((size_t)lyr * QKVD + n_new) * DIM + c4 * 4) / 2;
    dst[0] = __halves2half2(__float2half(v.x), __float2half(v.y));
    dst[1] = __halves2half2(__float2half(v.z), __float2half(v.w));
    if (c4 == 0) bdst[(size_t)lyr * QKVD + n_new] = bsrc[(size_t)lyr * QKVD + n];
}

__global__ __launch_bounds__(256) void ln_split_warp(
    const float* __restrict__ x, const float* __restrict__ w,
    const float* __restrict__ b, __half* __restrict__ y16)
{
    int row = blockIdx.x * 8 + (threadIdx.x >> 5);
    if (row >= ROWS) return;
    int lane = threadIdx.x & 31;
    const float4* xr = (const float4*)(x + (size_t)row * DIM);
    float4 vx[6];
    float s = 0.f;
#pragma unroll
    for (int i = 0; i < 6; i++) {
        vx[i] = xr[lane + 32 * i];
        s += (vx[i].x + vx[i].y) + (vx[i].z + vx[i].w);
    }
    s = wred_sum(s);
    float mean = s * (1.0f / 768.f);
    float s2 = 0.f;
#pragma unroll
    for (int i = 0; i < 6; i++) {
        float a0 = vx[i].x - mean, a1 = vx[i].y - mean;
        float a2 = vx[i].z - mean, a3 = vx[i].w - mean;
        s2 += a0 * a0 + a1 * a1 + a2 * a2 + a3 * a3;
    }
    s2 = wred_sum(s2);
    float inv = rsqrtf(s2 * (1.0f / 768.f) + 1e-5f);
    const float4* wr = (const float4*)w;
    const float4* br = (const float4*)b;
    __half2* yh = (__half2*)(y16 + (size_t)row * KP2_D);
    __half2* yl = (__half2*)(y16 + (size_t)row * KP2_D + DIM);
#pragma unroll
    for (int i = 0; i < 6; i++) {
        int c4 = lane + 32 * i;
        float4 w4 = wr[c4], b4 = br[c4];
        float v0 = (vx[i].x - mean) * inv * w4.x + b4.x;
        float v1 = (vx[i].y - mean) * inv * w4.y + b4.y;
        float v2 = (vx[i].z - mean) * inv * w4.z + b4.z;
        float v3 = (vx[i].w - mean) * inv * w4.w + b4.w;
        __half h0 = __float2half(v0), h1 = __float2half(v1);
        __half h2 = __float2half(v2), h3 = __float2half(v3);
        yh[c4 * 2]     = __halves2half2(h0, h1);
        yh[c4 * 2 + 1] = __halves2half2(h2, h3);
        yl[c4 * 2]     = __halves2half2(__float2half(v0 - __half2float(h0)),
                                        __float2half(v1 - __half2float(h1)));
        yl[c4 * 2 + 1] = __halves2half2(__float2half(v2 - __half2float(h2)),
                                        __float2half(v3 - __half2float(h3)));
    }
}

__global__ void im2col_split(const float* __restrict__ img, __half* __restrict__ a16)
{
    int idx = blockIdx.x * blockDim.x + threadIdx.x;
    if (idx >= PATCH_ROWS * DIM) return;
    int e = idx % DIM;
    int m = idx / DIM;
    int b = m / NPATCH, p = m % NPATCH;
    int gr = p / 14, gc = p % 14;
    int c = e % 3;
    int pp = e / 3;
    int pr = pp / 16, pc = pp % 16;
    float v = img[(((size_t)b * 3 + c) * 224 + gr * 16 + pr) * 224 + gc * 16 + pc];
    __half hi = __float2half(v);
    __half* dst = a16 + (size_t)m * KP2_D;
    dst[e] = hi;
    dst[DIM + e] = __float2half(v - __half2float(hi));
}

__global__ void assemble_kernel(const float* __restrict__ tokens,
                                const float* __restrict__ cls,
                                const float* __restrict__ pos,
                                float* __restrict__ x)
{
    int idx = blockIdx.x * blockDim.x + threadIdx.x;
    if (idx >= ROWS * DIM) return;
    int d = idx % DIM;
    int r = idx / DIM;
    int b = r / TOK, n = r % TOK;
    float v = (n == 0) ? cls[d] : tokens[((size_t)b * NPATCH + (n - 1)) * DIM + d];
    x[idx] = v + pos[(size_t)n * DIM + d];
}

// ===== attention: 2 queries per warp, fp16 K/V in smem =====
#define ATT_PAD 33
#define ATT2_SMEM ((2*TOK*ATT_PAD + 16*ATT_PAD) * 4 + 16*200*4)

__global__ __launch_bounds__(256) void attn2(
    const __half* __restrict__ Q, const __half* __restrict__ K,
    const __half* __restrict__ V, __half* __restrict__ a16)
{
    extern __shared__ char smraw[];
    __half2* ks2 = (__half2*)smraw;
    __half2* vs2 = ks2 + TOK * ATT_PAD;
    __half2* qs2 = vs2 + TOK * ATT_PAD;
    float*   sc  = (float*)(qs2 + 16 * ATT_PAD);

    int bh = blockIdx.x;
    int b = bh / HEADS, h = bh % HEADS;
    int tid = threadIdx.x, lane = tid & 31, w = tid >> 5;
    const __half2* Qb = (const __half2*)(Q + (size_t)bh * TOK * DHD);
    const __half2* Kb = (const __half2*)(K + (size_t)bh * TOK * DHD);
    const __half2* Vb = (const __half2*)(V + (size_t)bh * TOK * DHD);

    for (int i = tid; i < TOK * 32; i += 256) {
        int n = i >> 5, d2 = i & 31;
        ks2[n * ATT_PAD + d2] = Kb[i];
        vs2[n * ATT_PAD + d2] = Vb[i];
    }
    __syncthreads();

    float* scw0 = sc + w * 400;
    float* scw1 = scw0 + 200;
    __half2* q0 = qs2 + (w * 2) * ATT_PAD;
    __half2* q1 = q0 + ATT_PAD;

    for (int base = 0; base < TOK; base += 16) {
        int nq0 = base + w * 2, nq1 = nq0 + 1;
        bool ok0 = (nq0 < TOK), ok1 = (nq1 < TOK);
        if (ok0) q0[lane] = Qb[(size_t)nq0 * 32 + lane];
        if (ok1) q1[lane] = Qb[(size_t)nq1 * 32 + lane];
        __syncwarp();
        if (!ok0) { continue; }
        float mx0 = -1e30f, mx1 = -1e30f;
        for (int kk = lane; kk < TOK; kk += 32) {
            float s0 = 0.f, s1 = 0.f;
#pragma unroll
            for (int d2 = 0; d2 < 32; d2++) {
                float2 kv  = __half22float2(ks2[kk * ATT_PAD + d2]);
                float2 qv0 = __half22float2(q0[d2]);
                float2 qv1 = __half22float2(q1[d2]);
                s0 += kv.x * qv0.x + kv.y * qv0.y;
                s1 += kv.x * qv1.x + kv.y * qv1.y;
            }
            scw0[kk] = s0 * 0.125f;
            scw1[kk] = s1 * 0.125f;
            mx0 = fmaxf(mx0, s0 * 0.125f);
            mx1 = fmaxf(mx1, s1 * 0.125f);
        }
#pragma unroll
        for (int o = 16; o > 0; o >>= 1) {
            mx0 = fmaxf(mx0, __shfl_xor_sync(0xffffffffu, mx0, o));
            mx1 = fmaxf(mx1, __shfl_xor_sync(0xffffffffu, mx1, o));
        }
        float sum0 = 0.f, sum1 = 0.f;
        for (int kk = lane; kk < TOK; kk += 32) {
            float p0 = expf(scw0[kk] - mx0);
            float p1 = expf(scw1[kk] - mx1);
            scw0[kk] = p0; scw1[kk] = p1;
            sum0 += p0; sum1 += p1;
        }
        sum0 = wred_sum(sum0); sum1 = wred_sum(sum1);
        float inv0 = 1.f / sum0, inv1 = 1.f / sum1;
        __syncwarp();
        float ax0 = 0.f, ay0 = 0.f, ax1 = 0.f, ay1 = 0.f;
        for (int kk = 0; kk < TOK; kk++) {
            float2 vv = __half22float2(vs2[kk * ATT_PAD + lane]);
            float p0 = scw0[kk], p1 = scw1[kk];
            ax0 += p0 * vv.x; ay0 += p0 * vv.y;
            ax1 += p1 * vv.x; ay1 += p1 * vv.y;
        }
        ax0 *= inv0; ay0 *= inv0; ax1 *= inv1; ay1 *= inv1;
        {
            size_t o0 = ((size_t)(b * TOK + nq0)) * KP2_D + h * DHD + lane * 2;
            __half h0 = __float2half(ax0), h1 = __float2half(ay0);
            a16[o0] = h0; a16[o0 + 1] = h1;
            a16[o0 + DIM]     = __float2half(ax0 - __half2float(h0));
            a16[o0 + DIM + 1] = __float2half(ay0 - __half2float(h1));
        }
        if (ok1) {
            size_t o1 = ((size_t)(b * TOK + nq1)) * KP2_D + h * DHD + lane * 2;
            __half h0 = __float2half(ax1), h1 = __float2half(ay1);
            a16[o1] = h0; a16[o1 + 1] = h1;
            a16[o1 + DIM]     = __float2half(ax1 - __half2float(h0));
            a16[o1 + DIM + 1] = __float2half(ay1 - __half2float(h1));
        }
        __syncwarp();
    }
}

// fp32 SGEMM for the tiny head (M=32)
__global__ __launch_bounds__(256) void sgemm(
    const float* __restrict__ A, int lda,
    const float* __restrict__ W, const float* __restrict__ bias,
    float* __restrict__ C, int ldc, int M, int N, int K, int act)
{
    __shared__ float As[16][128];
    __shared__ float Bs[16][64];
    int tid = threadIdx.x;
    int tx = tid & 15, ty = tid >> 4;
    int row0 = blockIdx.y * 128;
    int col0 = blockIdx.x * 64;
    float acc[8][4];
#pragma unroll
    for (int i = 0; i < 8; i++)
#pragma unroll
        for (int j = 0; j < 4; j++) acc[i][j] = 0.f;
    for (int k0 = 0; k0 < K; k0 += 16) {
#pragma unroll
        for (int i = 0; i < 2; i++) {
            int idx = tid + i * 256;
            int r = idx >> 2, c = (idx & 3) << 2;
            int gr = row0 + r;
            float4 v = make_float4(0.f, 0.f, 0.f, 0.f);
            if (gr < M) v = *(const float4*)(A + (size_t)gr * lda + k0 + c);
            As[c + 0][r] = v.x; As[c + 1][r] = v.y; As[c + 2][r] = v.z; As[c + 3][r] = v.w;
        }
        {
            int n = tid >> 2, c = (tid & 3) << 2;
            int gn = col0 + n;
            float4 v = make_float4(0.f, 0.f, 0.f, 0.f);
            if (gn < N) v = *(const float4*)(W + (size_t)gn * K + k0 + c);
            Bs[c + 0][n] = v.x; Bs[c + 1][n] = v.y; Bs[c + 2][n] = v.z; Bs[c + 3][n] = v.w;
        }
        __syncthreads();
#pragma unroll
        for (int kk = 0; kk < 16; kk++) {
            float4 a0 = *(const float4*)&As[kk][ty * 8];
            float4 a1 = *(const float4*)&As[kk][ty * 8 + 4];
            float4 bb = *(const float4*)&Bs[kk][tx * 4];
            float av[8] = {a0.x, a0.y, a0.z, a0.w, a1.x, a1.y, a1.z, a1.w};
            float bv[4] = {bb.x, bb.y, bb.z, bb.w};
#pragma unroll
            for (int i = 0; i < 8; i++)
#pragma unroll
                for (int j = 0; j < 4; j++) acc[i][j] += av[i] * bv[j];
        }
        __syncthreads();
    }
#pragma unroll
    for (int i = 0; i < 8; i++) {
        int gr = row0 + ty * 8 + i;
        if (gr >= M) continue;
#pragma unroll
        for (int j = 0; j < 4; j++) {
            int gn = col0 + tx * 4 + j;
            if (gn >= N) continue;
            float v = acc[i][j];
            if (bias) v += bias[gn];
            if (act == 2) v = tanhf(v);
            C[(size_t)gr * ldc + gn] = v;
        }
    }
}

extern "C" void kernel_launch(void* const* d_in, const int* in_sizes, int n_in,
                              void* d_out, int out_size)
{
    const float* img     = (const float*)d_in[0];
    const float* patch_w = (const float*)d_in[1];
    const float* patch_b = (const float*)d_in[2];
    const float* cls_tok = (const float*)d_in[3];
    const float* pos_emb = (const float*)d_in[4];
    const float* ln1_w   = (const float*)d_in[5];
    const float* ln1_b   = (const float*)d_in[6];
    const float* qkv_w   = (const float*)d_in[7];
    const float* qkv_b   = (const float*)d_in[8];
    const float* proj_w  = (const float*)d_in[9];
    const float* proj_b  = (const float*)d_in[10];
    const float* ln2_w   = (const float*)d_in[11];
    const float* ln2_b   = (const float*)d_in[12];
    const float* ff1_w   = (const float*)d_in[13];
    const float* ff1_b   = (const float*)d_in[14];
    const float* ff2_w   = (const float*)d_in[15];
    const float* ff2_b   = (const float*)d_in[16];
    const float* head1_w = (const float*)d_in[17];
    const float* head1_b = (const float*)d_in[18];
    const float* head2_w = (const float*)d_in[19];
    const float* head2_b = (const float*)d_in[20];
    float* out = (float*)d_out;

    float *x, *tok, *hh, *qb;
    __half *q, *k, *v, *a16, *f16, *wp, *wq, *wpr, *wf1, *wf2;
    cudaGetSymbolAddress((void**)&x,   g_x);
    cudaGetSymbolAddress((void**)&q,   g_q16);
    cudaGetSymbolAddress((void**)&k,   g_k16);
    cudaGetSymbolAddress((void**)&v,   g_v16);
    cudaGetSymbolAddress((void**)&tok, g_tok);
    cudaGetSymbolAddress((void**)&hh,  g_hh);
    cudaGetSymbolAddress((void**)&qb,  g_qb);
    cudaGetSymbolAddress((void**)&a16, g_a16);
    cudaGetSymbolAddress((void**)&f16, g_f16);
    cudaGetSymbolAddress((void**)&wp,  g_wp16);
    cudaGetSymbolAddress((void**)&wq,  g_wqkv16);
    cudaGetSymbolAddress((void**)&wpr, g_wpr16);
    cudaGetSymbolAddress((void**)&wf1, g_wf1_16);
    cudaGetSymbolAddress((void**)&wf2, g_wf2_16);

    cudaFuncSetAttribute(hgemm,      cudaFuncAttributeMaxDynamicSharedMemorySize, HG_SMEM);
    cudaFuncSetAttribute(hgemm_bm64, cudaFuncAttributeMaxDynamicSharedMemorySize, HGB_SMEM);
    cudaFuncSetAttribute(attn2,      cudaFuncAttributeMaxDynamicSharedMemorySize, ATT2_SMEM);

    long t4;
    t4 = (long)DIM * DIM / 4;
    convert_w<<<(unsigned)((t4 + 255) / 256), 256>>>((const float4*)patch_w, (__half2*)wp, t4);
    t4 = 12L * QKVD * DIM / 4;
    convert_wqkv<<<(unsigned)((t4 + 255) / 256), 256>>>((const float4*)qkv_w, (__half2*)wq,
                                                        qkv_b, qb);
    t4 = 12L * DIM * DIM / 4;
    convert_w<<<(unsigned)((t4 + 255) / 256), 256>>>((const float4*)proj_w, (__half2*)wpr, t4);
    t4 = 12L * FFD * DIM / 4;
    convert_w<<<(unsigned)((t4 + 255) / 256), 256>>>((const float4*)ff1_w, (__half2*)wf1, t4);
    t4 = 12L * DIM * FFD / 4;
    convert_w<<<(unsigned)((t4 + 255) / 256), 256>>>((const float4*)ff2_w, (__half2*)wf2, t4);

    {
        int tot = PATCH_ROWS * DIM;
        im2col_split<<<(tot + 255) / 256, 256>>>(img, a16);
        hgemm<<<dim3(6, 49), 256, HG_SMEM>>>(a16, wp, DIM, patch_b, (const float*)0,
                                             tok, (__half*)0, (__half*)0, (__half*)0, (__half*)0,
                                             DIM, PATCH_ROWS, 0, 1);
        int tot2 = ROWS * DIM;
        assemble_kernel<<<(tot2 + 255) / 256, 256>>>(tok, cls_tok, pos_emb, x);
    }

    for (int l = 0; l < 12; l++) {
        ln_split_warp<<<(ROWS + 7) / 8, 256>>>(x, ln1_w + (size_t)l * DIM, ln1_b + (size_t)l * DIM, a16);
        hgemm<<<dim3(18, 50), 256, HG_SMEM>>>(a16, wq + (size_t)l * QKVD * DIM, DIM,
                                              qb + (size_t)l * QKVD, (const float*)0,
                                              (float*)0, (__half*)0, q, k, v,
                                              QKVD, ROWS, 3, 0);
        attn2<<<BATCH * HEADS, 256, ATT2_SMEM>>>(q, k, v, a16);
        hgemm_bm64<<<dim3(6, 99), 256, HGB_SMEM>>>(a16, wpr + (size_t)l * DIM * DIM, DIM,
                                                   proj_b + (size_t)l * DIM, x,
                                                   x, DIM, ROWS, 1);
        ln_split_warp<<<(ROWS + 7) / 8, 256>>>(x, ln2_w + (size_t)l * DIM, ln2_b + (size_t)l * DIM, a16);
        hgemm<<<dim3(24, 50), 256, HG_SMEM>>>(a16, wf1 + (size_t)l * FFD * DIM, DIM,
                                              ff1_b + (size_t)l * FFD, (const float*)0,
                                              (float*)0, f16, (__half*)0, (__half*)0, (__half*)0,
                                              FFD, ROWS, 2, 0 /* FF1 single product */);
        hgemm_bm64<<<dim3(6, 99), 256, HGB_SMEM>>>(f16, wf2 + (size_t)l * DIM * FFD, FFD,
                                                   ff2_b + (size_t)l * DIM, x,
                                                   x, DIM, ROWS, 1);
    }

    sgemm<<<dim3(48, 1), 256>>>(x, TOK * DIM, head1_w, head1_b, hh, FFD, BATCH, FFD, DIM, 2);
    sgemm<<<dim3(16, 1), 256>>>(hh, FFD, head2_w, head2_b, out, NCLSD, BATCH, NCLSD, FFD, 0);
}

// round 16
// speedup vs baseline: 1.3906x; 1.0873x over previous
#include <cuda_runtime.h>
#include <cuda_fp16.h>
#include <math.h>
#include <stdint.h>

#define BATCH 32
#define TOK 197
#define ROWS (BATCH*TOK)
#define MPAD 6400
#define DIM 768
#define HEADS 12
#define DHD 64
#define FFD 3072
#define QKVD 2304
#define NPATCH 196
#define PATCH_ROWS (BATCH*NPATCH)
#define NCLSD 1000
#define KP2_D (2*DIM)
#define KP2_F (2*FFD)

__device__ float  g_x   [ROWS*DIM];
__device__ __align__(128) __half g_q16 [BATCH*HEADS*TOK*DHD];
__device__ __align__(128) __half g_k16 [BATCH*HEADS*TOK*DHD];
__device__ __align__(128) __half g_v16 [BATCH*HEADS*TOK*DHD];
__device__ float  g_tok [PATCH_ROWS*DIM];
__device__ float  g_hh  [BATCH*FFD];
__device__ float  g_qb  [12*QKVD];
__device__ __align__(128) __half g_a16 [MPAD*KP2_D];
__device__ __align__(128) __half g_f16 [(size_t)MPAD*KP2_F];
__device__ __align__(128) __half g_wp16  [DIM*DIM];
__device__ __align__(128) __half g_wqkv16[(size_t)12*QKVD*DIM];
__device__ __align__(128) __half g_wpr16 [(size_t)12*DIM*DIM];
__device__ __align__(128) __half g_wf1_16[(size_t)12*FFD*DIM];
__device__ __align__(128) __half g_wf2_16[(size_t)12*DIM*FFD];

__device__ __forceinline__ uint32_t smem_u32(const void* p) {
    uint32_t a;
    asm("{ .reg .u64 t; cvta.to.shared.u64 t, %1; cvt.u32.u64 %0, t; }" : "=r"(a) : "l"(p));
    return a;
}
__device__ __forceinline__ void cp_async16(uint32_t s, const void* g) {
    asm volatile("cp.async.cg.shared.global [%0], [%1], 16;\n" :: "r"(s), "l"(g));
}
#define CP_COMMIT() asm volatile("cp.async.commit_group;\n" ::: "memory")
#define CP_WAIT(n)  asm volatile("cp.async.wait_group %0;\n" :: "n"(n) : "memory")

__device__ __forceinline__ void ldsm_x4(uint32_t& r0, uint32_t& r1, uint32_t& r2, uint32_t& r3,
                                        uint32_t addr) {
    asm volatile("ldmatrix.sync.aligned.m8n8.x4.shared.b16 {%0,%1,%2,%3}, [%4];"
                 : "=r"(r0), "=r"(r1), "=r"(r2), "=r"(r3) : "r"(addr));
}
__device__ __forceinline__ void mma16816(float* c, const uint32_t* a, const uint32_t* b) {
    asm volatile("mma.sync.aligned.m16n8k16.row.col.f32.f16.f16.f32 "
        "{%0,%1,%2,%3}, {%4,%5,%6,%7}, {%8,%9}, {%0,%1,%2,%3};"
        : "+f"(c[0]), "+f"(c[1]), "+f"(c[2]), "+f"(c[3])
        : "r"(a[0]), "r"(a[1]), "r"(a[2]), "r"(a[3]), "r"(b[0]), "r"(b[1]));
}
__device__ __forceinline__ float gelu_f(float v) {
    return 0.5f * v * (1.0f + erff(v * 0.70710678118654752f));
}
__device__ __forceinline__ float wred_sum(float v) {
#pragma unroll
    for (int o = 16; o > 0; o >>= 1) v += __shfl_xor_sync(0xffffffffu, v, o);
    return v;
}

// ===== split-fp16 HMMA GEMM: BM=128 BN=128, Kc=64, 2-stage =====
#define STG 49152
#define HG_SMEM (2*STG)

__global__ __launch_bounds__(256, 2) void hgemm(
    const __half* __restrict__ A, const __half* __restrict__ B, int K,
    const float* __restrict__ bias, const float* __restrict__ res,
    float* __restrict__ outF, __half* __restrict__ out16,
    __half* __restrict__ gq, __half* __restrict__ gk, __half* __restrict__ gv,
    int ldc, int M, int mode, int lo)
{
    extern __shared__ char smraw[];
    uint32_t smb = smem_u32(smraw);
    int tid = threadIdx.x;
    int lane = tid & 31, wid = tid >> 5;
    int warp_m = wid & 1, warp_n = wid >> 1;
    int row0 = blockIdx.y * 128, col0 = blockIdx.x * 128;

    uint32_t ld_slot[4]; int ld_r[4], ld_c[4];
#pragma unroll
    for (int j = 0; j < 4; j++) {
        int idx = tid + j * 256;
        ld_r[j] = idx >> 3; ld_c[j] = idx & 7;
        ld_slot[j] = (uint32_t)(ld_r[j] * 128 + ((ld_c[j] ^ (ld_r[j] & 7)) << 4));
    }

    int g = lane >> 3, l = lane & 7;
    uint32_t a_roff[4], a_xor[4];
#pragma unroll
    for (int mi = 0; mi < 4; mi++) {
        int r = warp_m * 64 + mi * 16 + (g & 1) * 8 + l;
        a_roff[mi] = r * 128; a_xor[mi] = r & 7;
    }
    uint32_t b_roff[2], b_xor[2];
#pragma unroll
    for (int j2 = 0; j2 < 2; j2++) {
        int r = warp_n * 32 + j2 * 16 + (g >> 1) * 8 + l;
        b_roff[j2] = r * 128; b_xor[j2] = r & 7;
    }

    float acc[4][4][4];
#pragma unroll
    for (int mi = 0; mi < 4; mi++)
#pragma unroll
        for (int nj = 0; nj < 4; nj++)
#pragma unroll
            for (int q = 0; q < 4; q++) acc[mi][nj][q] = 0.f;

    const int KT = K >> 6;
    const size_t strA = (size_t)(2 * K);
    const size_t strB = (size_t)K;
    const __half* gA = A + (size_t)row0 * strA;
    const __half* gB = B + (size_t)col0 * strB;

#define LOAD_ST(s, kb) do { \
    uint32_t sa = smb + (uint32_t)(s) * STG; \
    _Pragma("unroll") \
    for (int j = 0; j < 4; j++) { \
        const __half* pa = gA + (size_t)ld_r[j] * strA + (size_t)(kb) * 64 + ld_c[j] * 8; \
        cp_async16(sa + ld_slot[j], pa); \
        if (lo) cp_async16(sa + 16384u + ld_slot[j], pa + K); \
        cp_async16(sa + 32768u + ld_slot[j], gB + (size_t)ld_r[j] * strB + (size_t)(kb) * 64 + ld_c[j] * 8); \
    } \
} while (0)

    LOAD_ST(0, 0); CP_COMMIT();

    for (int i = 0; i < KT; i++) {
        CP_WAIT(0);
        __syncthreads();
        if (i + 1 < KT) { LOAD_ST((i + 1) & 1, i + 1); CP_COMMIT(); }

        uint32_t ah_b = smb + (uint32_t)(i & 1) * STG;
        uint32_t al_b = ah_b + 16384u;
        uint32_t bh_b = ah_b + 32768u;
#pragma unroll
        for (int ks = 0; ks < 4; ks++) {
            uint32_t cha = (uint32_t)(ks * 2 + (g >> 1));
            uint32_t chb = (uint32_t)(ks * 2 + (g & 1));
            uint32_t afh[4][4], bf[4][2];
#pragma unroll
            for (int mi = 0; mi < 4; mi++)
                ldsm_x4(afh[mi][0], afh[mi][1], afh[mi][2], afh[mi][3],
                        ah_b + a_roff[mi] + ((cha ^ a_xor[mi]) << 4));
#pragma unroll
            for (int j2 = 0; j2 < 2; j2++)
                ldsm_x4(bf[j2 * 2][0], bf[j2 * 2][1], bf[j2 * 2 + 1][0], bf[j2 * 2 + 1][1],
                        bh_b + b_roff[j2] + ((chb ^ b_xor[j2]) << 4));
#pragma unroll
            for (int mi = 0; mi < 4; mi++)
#pragma unroll
                for (int nj = 0; nj < 4; nj++)
                    mma16816(acc[mi][nj], afh[mi], bf[nj]);
            if (lo) {
                uint32_t afl[4][4];
#pragma unroll
                for (int mi = 0; mi < 4; mi++)
                    ldsm_x4(afl[mi][0], afl[mi][1], afl[mi][2], afl[mi][3],
                            al_b + a_roff[mi] + ((cha ^ a_xor[mi]) << 4));
#pragma unroll
                for (int mi = 0; mi < 4; mi++)
#pragma unroll
                    for (int nj = 0; nj < 4; nj++)
                        mma16816(acc[mi][nj], afl[mi], bf[nj]);
            }
        }
    }

    int qrow = lane >> 2, qcol = (lane & 3) * 2;
#pragma unroll
    for (int mi = 0; mi < 4; mi++) {
        int rbase = row0 + warp_m * 64 + mi * 16 + qrow;
#pragma unroll
        for (int half = 0; half < 2; half++) {
            int r = rbase + half * 8;
            if (r >= M) continue;
            int rb = r / TOK, rn = r - rb * TOK;
#pragma unroll
            for (int nj = 0; nj < 4; nj++) {
                int c = col0 + warp_n * 32 + nj * 8 + qcol;
                float v0 = acc[mi][nj][half * 2 + 0] + __ldg(bias + c);
                float v1 = acc[mi][nj][half * 2 + 1] + __ldg(bias + c + 1);
                if (mode == 2) {
                    float g0 = gelu_f(v0), g1 = gelu_f(v1);
                    __half h0 = __float2half(g0), h1 = __float2half(g1);
                    __half l0 = __float2half(g0 - __half2float(h0));
                    __half l1 = __float2half(g1 - __half2float(h1));
                    __half* o = out16 + (size_t)r * (2 * ldc) + c;
                    *(__half2*)(o)       = __halves2half2(h0, h1);
                    *(__half2*)(o + ldc) = __halves2half2(l0, l1);
                } else if (mode == 3) {
                    int ss = c / 768;
                    int rem = c - ss * 768;
                    int hh = rem >> 6, dd = rem & 63;
                    __half* dst = (ss == 0) ? gq : (ss == 1) ? gk : gv;
                    *(__half2*)(dst + (((size_t)(rb * HEADS + hh)) * TOK + rn) * DHD + dd) =
                        __halves2half2(__float2half(v0), __float2half(v1));
                } else {
                    float* o = outF + (size_t)r * ldc + c;
                    if (mode == 1) {
                        const float* rr = res + (size_t)r * ldc + c;
                        v0 += rr[0]; v1 += rr[1];
                    }
                    *(float2*)o = make_float2(v0, v1);
                }
            }
        }
    }
}

// ===== hgemm_bm64: BM=64, BN=128 (tail-friendly); lo flag =====
#define STGB 32768
#define HGB_SMEM (2*STGB)

__global__ __launch_bounds__(256, 2) void hgemm_bm64(
    const __half* __restrict__ A, const __half* __restrict__ B, int K,
    const float* __restrict__ bias, const float* __restrict__ res,
    float* __restrict__ outF, int ldc, int M, int mode, int lo)
{
    extern __shared__ char smraw[];
    uint32_t smb = smem_u32(smraw);
    int tid = threadIdx.x;
    int lane = tid & 31, wid = tid >> 5;
    int warp_m = wid & 1, warp_n = wid >> 1;
    int row0 = blockIdx.y * 64, col0 = blockIdx.x * 128;

    uint32_t ld_slot[4]; int ld_r[4], ld_c[4];
#pragma unroll
    for (int j = 0; j < 4; j++) {
        int idx = tid + j * 256;
        ld_r[j] = idx >> 3; ld_c[j] = idx & 7;
        ld_slot[j] = (uint32_t)(ld_r[j] * 128 + ((ld_c[j] ^ (ld_r[j] & 7)) << 4));
    }

    int g = lane >> 3, l = lane & 7;
    uint32_t a_roff[2], a_xor[2];
#pragma unroll
    for (int mi = 0; mi < 2; mi++) {
        int r = warp_m * 32 + mi * 16 + (g & 1) * 8 + l;
        a_roff[mi] = r * 128; a_xor[mi] = r & 7;
    }
    uint32_t b_roff[2], b_xor[2];
#pragma unroll
    for (int j2 = 0; j2 < 2; j2++) {
        int r = warp_n * 32 + j2 * 16 + (g >> 1) * 8 + l;
        b_roff[j2] = r * 128; b_xor[j2] = r & 7;
    }

    float acc[2][4][4];
#pragma unroll
    for (int mi = 0; mi < 2; mi++)
#pragma unroll
        for (int nj = 0; nj < 4; nj++)
#pragma unroll
            for (int q = 0; q < 4; q++) acc[mi][nj][q] = 0.f;

    const int KT = K >> 6;
    const size_t strA = (size_t)(2 * K);
    const size_t strB = (size_t)K;
    const __half* gA = A + (size_t)row0 * strA;
    const __half* gB = B + (size_t)col0 * strB;

#define LOAD_STB(s, kb) do { \
    uint32_t sa = smb + (uint32_t)(s) * STGB; \
    _Pragma("unroll") \
    for (int j = 0; j < 2; j++) { \
        const __half* pa = gA + (size_t)ld_r[j] * strA + (size_t)(kb) * 64 + ld_c[j] * 8; \
        cp_async16(sa + ld_slot[j], pa); \
        if (lo) cp_async16(sa + 8192u + ld_slot[j], pa + K); \
    } \
    _Pragma("unroll") \
    for (int j = 0; j < 4; j++) { \
        cp_async16(sa + 16384u + ld_slot[j], gB + (size_t)ld_r[j] * strB + (size_t)(kb) * 64 + ld_c[j] * 8); \
    } \
} while (0)

    LOAD_STB(0, 0); CP_COMMIT();

    for (int i = 0; i < KT; i++) {
        CP_WAIT(0);
        __syncthreads();
        if (i + 1 < KT) { LOAD_STB((i + 1) & 1, i + 1); CP_COMMIT(); }

        uint32_t ah_b = smb + (uint32_t)(i & 1) * STGB;
        uint32_t al_b = ah_b + 8192u;
        uint32_t bh_b = ah_b + 16384u;
#pragma unroll
        for (int ks = 0; ks < 4; ks++) {
            uint32_t cha = (uint32_t)(ks * 2 + (g >> 1));
            uint32_t chb = (uint32_t)(ks * 2 + (g & 1));
            uint32_t afh[2][4], bf[4][2];
#pragma unroll
            for (int mi = 0; mi < 2; mi++)
                ldsm_x4(afh[mi][0], afh[mi][1], afh[mi][2], afh[mi][3],
                        ah_b + a_roff[mi] + ((cha ^ a_xor[mi]) << 4));
#pragma unroll
            for (int j2 = 0; j2 < 2; j2++)
                ldsm_x4(bf[j2 * 2][0], bf[j2 * 2][1], bf[j2 * 2 + 1][0], bf[j2 * 2 + 1][1],
                        bh_b + b_roff[j2] + ((chb ^ b_xor[j2]) << 4));
#pragma unroll
            for (int mi = 0; mi < 2; mi++)
#pragma unroll
                for (int nj = 0; nj < 4; nj++)
                    mma16816(acc[mi][nj], afh[mi], bf[nj]);
            if (lo) {
                uint32_t afl[2][4];
#pragma unroll
                for (int mi = 0; mi < 2; mi++)
                    ldsm_x4(afl[mi][0], afl[mi][1], afl[mi][2], afl[mi][3],
                            al_b + a_roff[mi] + ((cha ^ a_xor[mi]) << 4));
#pragma unroll
                for (int mi = 0; mi < 2; mi++)
#pragma unroll
                    for (int nj = 0; nj < 4; nj++)
                        mma16816(acc[mi][nj], afl[mi], bf[nj]);
            }
        }
    }

    int qrow = lane >> 2, qcol = (lane & 3) * 2;
#pragma unroll
    for (int mi = 0; mi < 2; mi++) {
        int rbase = row0 + warp_m * 32 + mi * 16 + qrow;
#pragma unroll
        for (int half = 0; half < 2; half++) {
            int r = rbase + half * 8;
            if (r >= M) continue;
#pragma unroll
            for (int nj = 0; nj < 4; nj++) {
                int c = col0 + warp_n * 32 + nj * 8 + qcol;
                float v0 = acc[mi][nj][half * 2 + 0] + __ldg(bias + c);
                float v1 = acc[mi][nj][half * 2 + 1] + __ldg(bias + c + 1);
                float* o = outF + (size_t)r * ldc + c;
                if (mode == 1) {
                    const float* rr = res + (size_t)r * ldc + c;
                    v0 += rr[0]; v1 += rr[1];
                }
                *(float2*)o = make_float2(v0, v1);
            }
        }
    }
}

// ===== helpers =====
__global__ void convert_w(const float4* __restrict__ W, __half2* __restrict__ W16, long total4)
{
    long idx = (long)blockIdx.x * blockDim.x + threadIdx.x;
    if (idx >= total4) return;
    float4 v = W[idx];
    W16[idx * 2]     = __halves2half2(__float2half(v.x), __float2half(v.y));
    W16[idx * 2 + 1] = __halves2half2(__float2half(v.z), __float2half(v.w));
}

__global__ void convert_wqkv(const float4* __restrict__ W, __half2* __restrict__ W16,
                             const float* __restrict__ bsrc, float* __restrict__ bdst)
{
    const int C4 = DIM / 4;
    long idx = (long)blockIdx.x * blockDim.x + threadIdx.x;
    if (idx >= 12L * QKVD * C4) return;
    long row = idx / C4; int c4 = (int)(idx - row * C4);
    int lyr = (int)(row / QKVD); int n = (int)(row - (long)lyr * QKVD);
    int h = n / 192, t = n - h * 192, d = t / 3, s = t - d * 3;
    int n_new = s * 768 + h * 64 + d;
    float4 v = W[idx];
    __half2* dst = W16 + (((size_t)lyr * QKVD + n_new) * DIM + c4 * 4) / 2;
    dst[0] = __halves2half2(__float2half(v.x), __float2half(v.y));
    dst[1] = __halves2half2(__float2half(v.z), __float2half(v.w));
    if (c4 == 0) bdst[(size_t)lyr * QKVD + n_new] = bsrc[(size_t)lyr * QKVD + n];
}

__global__ __launch_bounds__(256) void ln_split_warp(
    const float* __restrict__ x, const float* __restrict__ w,
    const float* __restrict__ b, __half* __restrict__ y16)
{
    int row = blockIdx.x * 8 + (threadIdx.x >> 5);
    if (row >= ROWS) return;
    int lane = threadIdx.x & 31;
    const float4* xr = (const float4*)(x + (size_t)row * DIM);
    float4 vx[6];
    float s = 0.f;
#pragma unroll
    for (int i = 0; i < 6; i++) {
        vx[i] = xr[lane + 32 * i];
        s += (vx[i].x + vx[i].y) + (vx[i].z + vx[i].w);
    }
    s = wred_sum(s);
    float mean = s * (1.0f / 768.f);
    float s2 = 0.f;
#pragma unroll
    for (int i = 0; i < 6; i++) {
        float a0 = vx[i].x - mean, a1 = vx[i].y - mean;
        float a2 = vx[i].z - mean, a3 = vx[i].w - mean;
        s2 += a0 * a0 + a1 * a1 + a2 * a2 + a3 * a3;
    }
    s2 = wred_sum(s2);
    float inv = rsqrtf(s2 * (1.0f / 768.f) + 1e-5f);
    const float4* wr = (const float4*)w;
    const float4* br = (const float4*)b;
    __half2* yh = (__half2*)(y16 + (size_t)row * KP2_D);
    __half2* yl = (__half2*)(y16 + (size_t)row * KP2_D + DIM);
#pragma unroll
    for (int i = 0; i < 6; i++) {
        int c4 = lane + 32 * i;
        float4 w4 = wr[c4], b4 = br[c4];
        float v0 = (vx[i].x - mean) * inv * w4.x + b4.x;
        float v1 = (vx[i].y - mean) * inv * w4.y + b4.y;
        float v2 = (vx[i].z - mean) * inv * w4.z + b4.z;
        float v3 = (vx[i].w - mean) * inv * w4.w + b4.w;
        __half h0 = __float2half(v0), h1 = __float2half(v1);
        __half h2 = __float2half(v2), h3 = __float2half(v3);
        yh[c4 * 2]     = __halves2half2(h0, h1);
        yh[c4 * 2 + 1] = __halves2half2(h2, h3);
        yl[c4 * 2]     = __halves2half2(__float2half(v0 - __half2float(h0)),
                                        __float2half(v1 - __half2float(h1)));
        yl[c4 * 2 + 1] = __halves2half2(__float2half(v2 - __half2float(h2)),
                                        __float2half(v3 - __half2float(h3)));
    }
}

__global__ void im2col_split(const float* __restrict__ img, __half* __restrict__ a16)
{
    int idx = blockIdx.x * blockDim.x + threadIdx.x;
    if (idx >= PATCH_ROWS * DIM) return;
    int e = idx % DIM;
    int m = idx / DIM;
    int b = m / NPATCH, p = m % NPATCH;
    int gr = p / 14, gc = p % 14;
    int c = e % 3;
    int pp = e / 3;
    int pr = pp / 16, pc = pp % 16;
    float v = img[(((size_t)b * 3 + c) * 224 + gr * 16 + pr) * 224 + gc * 16 + pc];
    __half hi = __float2half(v);
    __half* dst = a16 + (size_t)m * KP2_D;
    dst[e] = hi;
    dst[DIM + e] = __float2half(v - __half2float(hi));
}

__global__ void assemble_kernel(const float* __restrict__ tokens,
                                const float* __restrict__ cls,
                                const float* __restrict__ pos,
                                float* __restrict__ x)
{
    int idx = blockIdx.x * blockDim.x + threadIdx.x;
    if (idx >= ROWS * DIM) return;
    int d = idx % DIM;
    int r = idx / DIM;
    int b = r / TOK, n = r % TOK;
    float v = (n == 0) ? cls[d] : tokens[((size_t)b * NPATCH + (n - 1)) * DIM + d];
    x[idx] = v + pos[(size_t)n * DIM + d];
}

// ===== attention: 2 queries per warp, fp16 K/V in smem =====
#define ATT_PAD 33
#define ATT2_SMEM ((2*TOK*ATT_PAD + 16*ATT_PAD) * 4 + 16*200*4)

__global__ __launch_bounds__(256) void attn2(
    const __half* __restrict__ Q, const __half* __restrict__ K,
    const __half* __restrict__ V, __half* __restrict__ a16)
{
    extern __shared__ char smraw[];
    __half2* ks2 = (__half2*)smraw;
    __half2* vs2 = ks2 + TOK * ATT_PAD;
    __half2* qs2 = vs2 + TOK * ATT_PAD;
    float*   sc  = (float*)(qs2 + 16 * ATT_PAD);

    int bh = blockIdx.x;
    int b = bh / HEADS, h = bh % HEADS;
    int tid = threadIdx.x, lane = tid & 31, w = tid >> 5;
    const __half2* Qb = (const __half2*)(Q + (size_t)bh * TOK * DHD);
    const __half2* Kb = (const __half2*)(K + (size_t)bh * TOK * DHD);
    const __half2* Vb = (const __half2*)(V + (size_t)bh * TOK * DHD);

    for (int i = tid; i < TOK * 32; i += 256) {
        int n = i >> 5, d2 = i & 31;
        ks2[n * ATT_PAD + d2] = Kb[i];
        vs2[n * ATT_PAD + d2] = Vb[i];
    }
    __syncthreads();

    float* scw0 = sc + w * 400;
    float* scw1 = scw0 + 200;
    __half2* q0 = qs2 + (w * 2) * ATT_PAD;
    __half2* q1 = q0 + ATT_PAD;

    for (int base = 0; base < TOK; base += 16) {
        int nq0 = base + w * 2, nq1 = nq0 + 1;
        bool ok0 = (nq0 < TOK), ok1 = (nq1 < TOK);
        if (ok0) q0[lane] = Qb[(size_t)nq0 * 32 + lane];
        if (ok1) q1[lane] = Qb[(size_t)nq1 * 32 + lane];
        __syncwarp();
        if (!ok0) { continue; }
        float mx0 = -1e30f, mx1 = -1e30f;
        for (int kk = lane; kk < TOK; kk += 32) {
            float s0 = 0.f, s1 = 0.f;
#pragma unroll
            for (int d2 = 0; d2 < 32; d2++) {
                float2 kv  = __half22float2(ks2[kk * ATT_PAD + d2]);
                float2 qv0 = __half22float2(q0[d2]);
                float2 qv1 = __half22float2(q1[d2]);
                s0 += kv.x * qv0.x + kv.y * qv0.y;
                s1 += kv.x * qv1.x + kv.y * qv1.y;
            }
            scw0[kk] = s0 * 0.125f;
            scw1[kk] = s1 * 0.125f;
            mx0 = fmaxf(mx0, s0 * 0.125f);
            mx1 = fmaxf(mx1, s1 * 0.125f);
        }
#pragma unroll
        for (int o = 16; o > 0; o >>= 1) {
            mx0 = fmaxf(mx0, __shfl_xor_sync(0xffffffffu, mx0, o));
            mx1 = fmaxf(mx1, __shfl_xor_sync(0xffffffffu, mx1, o));
        }
        float sum0 = 0.f, sum1 = 0.f;
        for (int kk = lane; kk < TOK; kk += 32) {
            float p0 = expf(scw0[kk] - mx0);
            float p1 = expf(scw1[kk] - mx1);
            scw0[kk] = p0; scw1[kk] = p1;
            sum0 += p0; sum1 += p1;
        }
        sum0 = wred_sum(sum0); sum1 = wred_sum(sum1);
        float inv0 = 1.f / sum0, inv1 = 1.f / sum1;
        __syncwarp();
        float ax0 = 0.f, ay0 = 0.f, ax1 = 0.f, ay1 = 0.f;
        for (int kk = 0; kk < TOK; kk++) {
            float2 vv = __half22float2(vs2[kk * ATT_PAD + lane]);
            float p0 = scw0[kk], p1 = scw1[kk];
            ax0 += p0 * vv.x; ay0 += p0 * vv.y;
            ax1 += p1 * vv.x; ay1 += p1 * vv.y;
        }
        ax0 *= inv0; ay0 *= inv0; ax1 *= inv1; ay1 *= inv1;
        {
            size_t o0 = ((size_t)(b * TOK + nq0)) * KP2_D + h * DHD + lane * 2;
            __half h0 = __float2half(ax0), h1 = __float2half(ay0);
            a16[o0] = h0; a16[o0 + 1] = h1;
            a16[o0 + DIM]     = __float2half(ax0 - __half2float(h0));
            a16[o0 + DIM + 1] = __float2half(ay0 - __half2float(h1));
        }
        if (ok1) {
            size_t o1 = ((size_t)(b * TOK + nq1)) * KP2_D + h * DHD + lane * 2;
            __half h0 = __float2half(ax1), h1 = __float2half(ay1);
            a16[o1] = h0; a16[o1 + 1] = h1;
            a16[o1 + DIM]     = __float2half(ax1 - __half2float(h0));
            a16[o1 + DIM + 1] = __float2half(ay1 - __half2float(h1));
        }
        __syncwarp();
    }
}

// fp32 SGEMM for the tiny head (M=32)
__global__ __launch_bounds__(256) void sgemm(
    const float* __restrict__ A, int lda,
    const float* __restrict__ W, const float* __restrict__ bias,
    float* __restrict__ C, int ldc, int M, int N, int K, int act)
{
    __shared__ float As[16][128];
    __shared__ float Bs[16][64];
    int tid = threadIdx.x;
    int tx = tid & 15, ty = tid >> 4;
    int row0 = blockIdx.y * 128;
    int col0 = blockIdx.x * 64;
    float acc[8][4];
#pragma unroll
    for (int i = 0; i < 8; i++)
#pragma unroll
        for (int j = 0; j < 4; j++) acc[i][j] = 0.f;
    for (int k0 = 0; k0 < K; k0 += 16) {
#pragma unroll
        for (int i = 0; i < 2; i++) {
            int idx = tid + i * 256;
            int r = idx >> 2, c = (idx & 3) << 2;
            int gr = row0 + r;
            float4 v = make_float4(0.f, 0.f, 0.f, 0.f);
            if (gr < M) v = *(const float4*)(A + (size_t)gr * lda + k0 + c);
            As[c + 0][r] = v.x; As[c + 1][r] = v.y; As[c + 2][r] = v.z; As[c + 3][r] = v.w;
        }
        {
            int n = tid >> 2, c = (tid & 3) << 2;
            int gn = col0 + n;
            float4 v = make_float4(0.f, 0.f, 0.f, 0.f);
            if (gn < N) v = *(const float4*)(W + (size_t)gn * K + k0 + c);
            Bs[c + 0][n] = v.x; Bs[c + 1][n] = v.y; Bs[c + 2][n] = v.z; Bs[c + 3][n] = v.w;
        }
        __syncthreads();
#pragma unroll
        for (int kk = 0; kk < 16; kk++) {
            float4 a0 = *(const float4*)&As[kk][ty * 8];
            float4 a1 = *(const float4*)&As[kk][ty * 8 + 4];
            float4 bb = *(const float4*)&Bs[kk][tx * 4];
            float av[8] = {a0.x, a0.y, a0.z, a0.w, a1.x, a1.y, a1.z, a1.w};
            float bv[4] = {bb.x, bb.y, bb.z, bb.w};
#pragma unroll
            for (int i = 0; i < 8; i++)
#pragma unroll
                for (int j = 0; j < 4; j++) acc[i][j] += av[i] * bv[j];
        }
        __syncthreads();
    }
#pragma unroll
    for (int i = 0; i < 8; i++) {
        int gr = row0 + ty * 8 + i;
        if (gr >= M) continue;
#pragma unroll
        for (int j = 0; j < 4; j++) {
            int gn = col0 + tx * 4 + j;
            if (gn >= N) continue;
            float v = acc[i][j];
            if (bias) v += bias[gn];
            if (act == 2) v = tanhf(v);
            C[(size_t)gr * ldc + gn] = v;
        }
    }
}

extern "C" void kernel_launch(void* const* d_in, const int* in_sizes, int n_in,
                              void* d_out, int out_size)
{
    const float* img     = (const float*)d_in[0];
    const float* patch_w = (const float*)d_in[1];
    const float* patch_b = (const float*)d_in[2];
    const float* cls_tok = (const float*)d_in[3];
    const float* pos_emb = (const float*)d_in[4];
    const float* ln1_w   = (const float*)d_in[5];
    const float* ln1_b   = (const float*)d_in[6];
    const float* qkv_w   = (const float*)d_in[7];
    const float* qkv_b   = (const float*)d_in[8];
    const float* proj_w  = (const float*)d_in[9];
    const float* proj_b  = (const float*)d_in[10];
    const float* ln2_w   = (const float*)d_in[11];
    const float* ln2_b   = (const float*)d_in[12];
    const float* ff1_w   = (const float*)d_in[13];
    const float* ff1_b   = (const float*)d_in[14];
    const float* ff2_w   = (const float*)d_in[15];
    const float* ff2_b   = (const float*)d_in[16];
    const float* head1_w = (const float*)d_in[17];
    const float* head1_b = (const float*)d_in[18];
    const float* head2_w = (const float*)d_in[19];
    const float* head2_b = (const float*)d_in[20];
    float* out = (float*)d_out;

    float *x, *tok, *hh, *qb;
    __half *q, *k, *v, *a16, *f16, *wp, *wq, *wpr, *wf1, *wf2;
    cudaGetSymbolAddress((void**)&x,   g_x);
    cudaGetSymbolAddress((void**)&q,   g_q16);
    cudaGetSymbolAddress((void**)&k,   g_k16);
    cudaGetSymbolAddress((void**)&v,   g_v16);
    cudaGetSymbolAddress((void**)&tok, g_tok);
    cudaGetSymbolAddress((void**)&hh,  g_hh);
    cudaGetSymbolAddress((void**)&qb,  g_qb);
    cudaGetSymbolAddress((void**)&a16, g_a16);
    cudaGetSymbolAddress((void**)&f16, g_f16);
    cudaGetSymbolAddress((void**)&wp,  g_wp16);
    cudaGetSymbolAddress((void**)&wq,  g_wqkv16);
    cudaGetSymbolAddress((void**)&wpr, g_wpr16);
    cudaGetSymbolAddress((void**)&wf1, g_wf1_16);
    cudaGetSymbolAddress((void**)&wf2, g_wf2_16);

    cudaFuncSetAttribute(hgemm,      cudaFuncAttributeMaxDynamicSharedMemorySize, HG_SMEM);
    cudaFuncSetAttribute(hgemm_bm64, cudaFuncAttributeMaxDynamicSharedMemorySize, HGB_SMEM);
    cudaFuncSetAttribute(attn2,      cudaFuncAttributeMaxDynamicSharedMemorySize, ATT2_SMEM);

    long t4;
    t4 = (long)DIM * DIM / 4;
    convert_w<<<(unsigned)((t4 + 255) / 256), 256>>>((const float4*)patch_w, (__half2*)wp, t4);
    t4 = 12L * QKVD * DIM / 4;
    convert_wqkv<<<(unsigned)((t4 + 255) / 256), 256>>>((const float4*)qkv_w, (__half2*)wq,
                                                        qkv_b, qb);
    t4 = 12L * DIM * DIM / 4;
    convert_w<<<(unsigned)((t4 + 255) / 256), 256>>>((const float4*)proj_w, (__half2*)wpr, t4);
    t4 = 12L * FFD * DIM / 4;
    convert_w<<<(unsigned)((t4 + 255) / 256), 256>>>((const float4*)ff1_w, (__half2*)wf1, t4);
    t4 = 12L * DIM * FFD / 4;
    convert_w<<<(unsigned)((t4 + 255) / 256), 256>>>((const float4*)ff2_w, (__half2*)wf2, t4);

    {
        int tot = PATCH_ROWS * DIM;
        im2col_split<<<(tot + 255) / 256, 256>>>(img, a16);
        hgemm<<<dim3(6, 49), 256, HG_SMEM>>>(a16, wp, DIM, patch_b, (const float*)0,
                                             tok, (__half*)0, (__half*)0, (__half*)0, (__half*)0,
                                             DIM, PATCH_ROWS, 0, 1);
        int tot2 = ROWS * DIM;
        assemble_kernel<<<(tot2 + 255) / 256, 256>>>(tok, cls_tok, pos_emb, x);
    }

    for (int l = 0; l < 12; l++) {
        ln_split_warp<<<(ROWS + 7) / 8, 256>>>(x, ln1_w + (size_t)l * DIM, ln1_b + (size_t)l * DIM, a16);
        hgemm<<<dim3(18, 50), 256, HG_SMEM>>>(a16, wq + (size_t)l * QKVD * DIM, DIM,
                                              qb + (size_t)l * QKVD, (const float*)0,
                                              (float*)0, (__half*)0, q, k, v,
                                              QKVD, ROWS, 3, 0);
        attn2<<<BATCH * HEADS, 256, ATT2_SMEM>>>(q, k, v, a16);
        hgemm_bm64<<<dim3(6, 99), 256, HGB_SMEM>>>(a16, wpr + (size_t)l * DIM * DIM, DIM,
                                                   proj_b + (size_t)l * DIM, x,
                                                   x, DIM, ROWS, 1, 1);
        ln_split_warp<<<(ROWS + 7) / 8, 256>>>(x, ln2_w + (size_t)l * DIM, ln2_b + (size_t)l * DIM, a16);
        hgemm<<<dim3(24, 50), 256, HG_SMEM>>>(a16, wf1 + (size_t)l * FFD * DIM, DIM,
                                              ff1_b + (size_t)l * FFD, (const float*)0,
                                              (float*)0, f16, (__half*)0, (__half*)0, (__half*)0,
                                              FFD, ROWS, 2, 0);
        hgemm_bm64<<<dim3(6, 99), 256, HGB_SMEM>>>(f16, wf2 + (size_t)l * DIM * FFD, FFD,
                                                   ff2_b + (size_t)l * DIM, x,
                                                   x, DIM, ROWS, 1, 0 /* FF2 single product */);
    }

    sgemm<<<dim3(48, 1), 256>>>(x, TOK * DIM, head1_w, head1_b, hh, FFD, BATCH, FFD, DIM, 2);
    sgemm<<<dim3(16, 1), 256>>>(hh, FFD, head2_w, head2_b, out, NCLSD, BATCH, NCLSD, FFD, 0);
}